// round 1
// baseline (speedup 1.0000x reference)
#include <cuda_runtime.h>
#include <math.h>

#define BATCH 128
#define TSEQ  64
#define VOCAB 10000
#define EMB   1024
#define HID   1024

typedef unsigned long long ull;

// ---------------- packed fp32x2 helpers (sm_103a FFMA2 path) ----------------
__device__ __forceinline__ ull pack2(float x, float y) {
    ull d; asm("mov.b64 %0, {%1, %2};" : "=l"(d) : "f"(x), "f"(y)); return d;
}
__device__ __forceinline__ float2 unpack2(ull v) {
    float2 r; asm("mov.b64 {%0, %1}, %2;" : "=f"(r.x), "=f"(r.y) : "l"(v)); return r;
}
__device__ __forceinline__ ull fma2(ull a, ull b, ull c) {
    ull d; asm("fma.rn.f32x2 %0, %1, %2, %3;" : "=l"(d) : "l"(a), "l"(b), "l"(c)); return d;
}

// ---------------- device scratch (allocation-free) ----------------
__device__ float g_x[TSEQ*BATCH*EMB];       // gathered embeddings, rows = t*B+b
__device__ float g_xu0[TSEQ*BATCH*HID];     // x-part of layer0 gate preacts (+bias)
__device__ float g_xr0[TSEQ*BATCH*HID];
__device__ float g_xc0[TSEQ*BATCH*HID];
__device__ float g_h0buf[2*BATCH*HID];      // ping-pong h0
__device__ float g_h1buf[2*BATCH*HID];      // ping-pong h1
__device__ float g_u0[BATCH*HID];
__device__ float g_rh0[BATCH*HID];
__device__ float g_u1[BATCH*HID];
__device__ float g_rh1[BATCH*HID];
__device__ float g_h1seq[TSEQ*BATCH*HID];   // h1 per step, rows = t*B+b

// ---------------- embedding gather: g_x[t*B+b][e] = emb[tok[b,t]][e] ----------------
__global__ void gather_kernel(const int* __restrict__ tok, const float* __restrict__ emb) {
    int row = blockIdx.x;            // t*B + b
    int t = row / BATCH, b = row % BATCH;
    int token = tok[b * TSEQ + t];
    const float4* src = (const float4*)(emb + (size_t)token * EMB);
    float4* dst = (float4*)(g_x + (size_t)row * EMB);
    dst[threadIdx.x] = src[threadIdx.x];    // 256 threads * 4 floats = 1024
}

__global__ void init_h(const float* __restrict__ ihs) {
    int i = blockIdx.x * blockDim.x + threadIdx.x;
    if (i < BATCH * HID) {
        g_h0buf[i] = ihs[i];
        g_h1buf[i] = ihs[BATCH * HID + i];
    }
}

__global__ void state_out(float* __restrict__ out, long long out_size) {
    long long i = (long long)blockIdx.x * blockDim.x + threadIdx.x;
    long long base = (long long)BATCH * TSEQ * VOCAB;
    if (i < BATCH * HID) {
        if (base + i < out_size)                out[base + i]              = g_h0buf[i];
        if (base + BATCH * HID + i < out_size)  out[base + BATCH*HID + i]  = g_h1buf[i];
    }
}

// ---------------- big GEMM: C = A[M,K] @ W[K,N] + bias ----------------
// MODE 0: C[m*N + n]                         (precompute x-projections)
// MODE 1: C[((m%B)*T + m/B)*N + n]           (logits remap, rows = t*B+b -> [B,T,V])
template<int MODE>
__global__ __launch_bounds__(256)
void big_gemm(const float* __restrict__ A, const float* __restrict__ W, int ldw,
              const float* __restrict__ bias, float* __restrict__ C,
              int M, int N, int K)
{
    __shared__ __align__(16) float As[16][132];
    __shared__ __align__(16) float Bs[16][132];
    const int tid = threadIdx.x;
    const int tx = tid & 15, ty = tid >> 4;       // 16 x 16
    const int m0 = blockIdx.x * 128;
    const int n0 = blockIdx.y * 128;

    ull acc[8][4];
    #pragma unroll
    for (int i = 0; i < 8; ++i)
        #pragma unroll
        for (int j = 0; j < 4; ++j) acc[i][j] = 0ull;

    for (int k0 = 0; k0 < K; k0 += 16) {
        // A tile 128x16, stored transposed
        #pragma unroll
        for (int l = 0; l < 2; ++l) {
            int idx = tid + l * 256;
            int m  = idx >> 2;
            int kq = (idx & 3) * 4;
            float4 v = *(const float4*)(A + (size_t)(m0 + m) * K + k0 + kq);
            As[kq+0][m] = v.x; As[kq+1][m] = v.y; As[kq+2][m] = v.z; As[kq+3][m] = v.w;
        }
        // W tile 16x128
        #pragma unroll
        for (int l = 0; l < 2; ++l) {
            int idx = tid + l * 256;
            int kk = idx >> 5;
            int c  = (idx & 31) * 4;
            const float* src = W + (size_t)(k0 + kk) * ldw + n0 + c;
            float4 v;
            if (MODE == 0 || n0 + c + 3 < N) {
                v = *(const float4*)src;
            } else {
                v.x = (n0+c+0 < N) ? src[0] : 0.f;
                v.y = (n0+c+1 < N) ? src[1] : 0.f;
                v.z = (n0+c+2 < N) ? src[2] : 0.f;
                v.w = 0.f;
            }
            Bs[kk][c+0]=v.x; Bs[kk][c+1]=v.y; Bs[kk][c+2]=v.z; Bs[kk][c+3]=v.w;
        }
        __syncthreads();
        #pragma unroll
        for (int kk = 0; kk < 16; ++kk) {
            ull ap[8];
            #pragma unroll
            for (int i = 0; i < 8; ++i) { float a = As[kk][ty + 16*i]; ap[i] = pack2(a, a); }
            ull bp[4];
            #pragma unroll
            for (int j = 0; j < 4; ++j) bp[j] = *(const ull*)&Bs[kk][tx*2 + 32*j];
            #pragma unroll
            for (int i = 0; i < 8; ++i)
                #pragma unroll
                for (int j = 0; j < 4; ++j)
                    acc[i][j] = fma2(ap[i], bp[j], acc[i][j]);
        }
        __syncthreads();
    }
    #pragma unroll
    for (int i = 0; i < 8; ++i) {
        int m = m0 + ty + 16*i;
        float* crow;
        if (MODE == 0) {
            crow = C + (size_t)m * N;
        } else {
            int b = m & (BATCH - 1);
            int t = m >> 7;
            crow = C + ((size_t)b * TSEQ + t) * N;
        }
        #pragma unroll
        for (int j = 0; j < 4; ++j) {
            int n = n0 + tx*2 + 32*j;
            float2 p = unpack2(acc[i][j]);
            if (n     < N) crow[n]   = p.x + bias[n];
            if (n + 1 < N) crow[n+1] = p.y + bias[n+1];
        }
    }
}

// ---------------- recurrence GEMM + fused GRU elementwise ----------------
// P[b,n] = add[b*stride + n] + A1[b,:]@W1[:,n] (+ A2[b,:]@W2[:,n])
// mode 0: out = sigmoid(P)                    (update gate)
// mode 1: out = sigmoid(P) * hprev            (reset gate * h)
// mode 2: c = tanh(P); out = u*hprev+(1-u)*c  (candidate + state update)
struct RArgs {
    const float* A1; const float* W1;
    const float* A2; const float* W2;
    const float* add; int add_stride;
    const float* hprev; const float* u;
    float* out; float* out2;
    int mode;
};
struct RPair { RArgs g[2]; };

__global__ __launch_bounds__(128)
void recur_kernel(RPair P)
{
    RArgs a = P.g[blockIdx.z];
    __shared__ __align__(16) float As[16][36];
    __shared__ __align__(16) float Bs[16][68];
    const int tid = threadIdx.x;
    const int tx = tid & 15, ty = tid >> 4;      // 16 x 8
    const int m0 = blockIdx.x * 32;
    const int n0 = blockIdx.y * 64;

    ull acc[4][2];
    #pragma unroll
    for (int i = 0; i < 4; ++i)
        #pragma unroll
        for (int j = 0; j < 2; ++j) acc[i][j] = 0ull;

    #pragma unroll 1
    for (int s = 0; s < 2; ++s) {
        const float* Ap = s ? a.A2 : a.A1;
        const float* Wp = s ? a.W2 : a.W1;
        if (Ap == nullptr) break;
        for (int k0 = 0; k0 < HID; k0 += 16) {
            {   // A tile 32x16 transposed
                int m  = tid >> 2;
                int kq = (tid & 3) * 4;
                float4 v = *(const float4*)(Ap + (size_t)(m0 + m) * HID + k0 + kq);
                As[kq+0][m]=v.x; As[kq+1][m]=v.y; As[kq+2][m]=v.z; As[kq+3][m]=v.w;
            }
            #pragma unroll
            for (int l = 0; l < 2; ++l) {   // W tile 16x64
                int idx = tid + l * 128;
                int kk = idx >> 4;
                int c  = (idx & 15) * 4;
                float4 v = *(const float4*)(Wp + (size_t)(k0 + kk) * HID + n0 + c);
                Bs[kk][c+0]=v.x; Bs[kk][c+1]=v.y; Bs[kk][c+2]=v.z; Bs[kk][c+3]=v.w;
            }
            __syncthreads();
            #pragma unroll
            for (int kk = 0; kk < 16; ++kk) {
                ull ap[4];
                #pragma unroll
                for (int i = 0; i < 4; ++i) { float av = As[kk][ty + 8*i]; ap[i] = pack2(av, av); }
                ull bp[2];
                #pragma unroll
                for (int j = 0; j < 2; ++j) bp[j] = *(const ull*)&Bs[kk][tx*2 + 32*j];
                #pragma unroll
                for (int i = 0; i < 4; ++i)
                    #pragma unroll
                    for (int j = 0; j < 2; ++j)
                        acc[i][j] = fma2(ap[i], bp[j], acc[i][j]);
            }
            __syncthreads();
        }
    }
    #pragma unroll
    for (int i = 0; i < 4; ++i) {
        int m = m0 + ty + 8*i;
        #pragma unroll
        for (int j = 0; j < 2; ++j) {
            int n = n0 + tx*2 + 32*j;
            int idx = m * HID + n;
            float2 p = unpack2(acc[i][j]);
            float px = p.x + a.add[(size_t)m * a.add_stride + n];
            float py = p.y + a.add[(size_t)m * a.add_stride + n + 1];
            if (a.mode == 0) {
                a.out[idx]   = 1.f / (1.f + expf(-px));
                a.out[idx+1] = 1.f / (1.f + expf(-py));
            } else if (a.mode == 1) {
                a.out[idx]   = (1.f / (1.f + expf(-px))) * a.hprev[idx];
                a.out[idx+1] = (1.f / (1.f + expf(-py))) * a.hprev[idx+1];
            } else {
                float ux = a.u[idx],   uy = a.u[idx+1];
                float cx = tanhf(px),  cy = tanhf(py);
                float hx = ux * a.hprev[idx]   + (1.f - ux) * cx;
                float hy = uy * a.hprev[idx+1] + (1.f - uy) * cy;
                a.out[idx] = hx; a.out[idx+1] = hy;
                if (a.out2) { a.out2[idx] = hx; a.out2[idx+1] = hy; }
            }
        }
    }
}

// ---------------- host orchestration ----------------
extern "C" void kernel_launch(void* const* d_in, const int* in_sizes, int n_in,
                              void* d_out, int out_size)
{
    const int*   tok  = (const int*)  d_in[0];
    const float* ihs  = (const float*)d_in[1];
    const float* emb  = (const float*)d_in[2];
    const float* Wout = (const float*)d_in[3];
    const float* bout = (const float*)d_in[4];
    const float* wu0  = (const float*)d_in[5];
    const float* bu0  = (const float*)d_in[6];
    const float* wr0  = (const float*)d_in[7];
    const float* br0  = (const float*)d_in[8];
    const float* wc0  = (const float*)d_in[9];
    const float* bc0  = (const float*)d_in[10];
    const float* wu1  = (const float*)d_in[11];
    const float* bu1  = (const float*)d_in[12];
    const float* wr1  = (const float*)d_in[13];
    const float* br1  = (const float*)d_in[14];
    const float* wc1  = (const float*)d_in[15];
    const float* bc1  = (const float*)d_in[16];

    float *p_x, *p_xu0, *p_xr0, *p_xc0, *p_h0, *p_h1;
    float *p_u0, *p_rh0, *p_u1, *p_rh1, *p_seq;
    cudaGetSymbolAddress((void**)&p_x,   g_x);
    cudaGetSymbolAddress((void**)&p_xu0, g_xu0);
    cudaGetSymbolAddress((void**)&p_xr0, g_xr0);
    cudaGetSymbolAddress((void**)&p_xc0, g_xc0);
    cudaGetSymbolAddress((void**)&p_h0,  g_h0buf);
    cudaGetSymbolAddress((void**)&p_h1,  g_h1buf);
    cudaGetSymbolAddress((void**)&p_u0,  g_u0);
    cudaGetSymbolAddress((void**)&p_rh0, g_rh0);
    cudaGetSymbolAddress((void**)&p_u1,  g_u1);
    cudaGetSymbolAddress((void**)&p_rh1, g_rh1);
    cudaGetSymbolAddress((void**)&p_seq, g_h1seq);

    // 1) gather embeddings for all (t, b)
    gather_kernel<<<TSEQ * BATCH, 256>>>(tok, emb);

    // 2) precompute layer-0 x-projections (+bias) as big GEMMs
    dim3 gpre(64, 8);
    big_gemm<0><<<gpre, 256>>>(p_x, wu0, HID, bu0, p_xu0, TSEQ*BATCH, HID, EMB);
    big_gemm<0><<<gpre, 256>>>(p_x, wr0, HID, br0, p_xr0, TSEQ*BATCH, HID, EMB);
    big_gemm<0><<<gpre, 256>>>(p_x, wc0, HID, bc0, p_xc0, TSEQ*BATCH, HID, EMB);

    // 3) initial hidden state
    init_h<<<(BATCH*HID + 255) / 256, 256>>>(ihs);

    // 4) sequential recurrence, 4 fused GEMM kernels per step
    const size_t EH = (size_t)EMB * HID;   // offset of h-rows in layer-0 weights
    const size_t HH = (size_t)HID * HID;   // offset of h-rows in layer-1 weights
    const size_t BH = (size_t)BATCH * HID;
    for (int t = 0; t < TSEQ; ++t) {
        int cur = t & 1, nxt = cur ^ 1;
        float* h0c = p_h0 + (size_t)cur * BH;
        float* h0n = p_h0 + (size_t)nxt * BH;
        float* h1c = p_h1 + (size_t)cur * BH;
        float* h1n = p_h1 + (size_t)nxt * BH;
        const float* xu = p_xu0 + (size_t)t * BH;
        const float* xr = p_xr0 + (size_t)t * BH;
        const float* xc = p_xc0 + (size_t)t * BH;

        RPair P1;  // layer0 u and r gates
        P1.g[0] = { h0c, wu0 + EH, nullptr, nullptr, xu, HID, h0c, nullptr, p_u0,  nullptr, 0 };
        P1.g[1] = { h0c, wr0 + EH, nullptr, nullptr, xr, HID, h0c, nullptr, p_rh0, nullptr, 1 };
        recur_kernel<<<dim3(4, 16, 2), 128>>>(P1);

        RPair P2;  // layer0 candidate + update
        P2.g[0] = { p_rh0, wc0 + EH, nullptr, nullptr, xc, HID, h0c, p_u0, h0n, nullptr, 2 };
        P2.g[1] = P2.g[0];
        recur_kernel<<<dim3(4, 16, 1), 128>>>(P2);

        RPair P3;  // layer1 u and r gates (x = h0n, K = 2048 via two sources)
        P3.g[0] = { h0n, wu1, h1c, wu1 + HH, bu1, 0, h1c, nullptr, p_u1,  nullptr, 0 };
        P3.g[1] = { h0n, wr1, h1c, wr1 + HH, br1, 0, h1c, nullptr, p_rh1, nullptr, 1 };
        recur_kernel<<<dim3(4, 16, 2), 128>>>(P3);

        RPair P4;  // layer1 candidate + update; also store h1 into sequence buffer
        P4.g[0] = { h0n, wc1, p_rh1, wc1 + HH, bc1, 0, h1c, p_u1, h1n, p_seq + (size_t)t * BH, 2 };
        P4.g[1] = P4.g[0];
        recur_kernel<<<dim3(4, 16, 1), 128>>>(P4);
    }

    // 5) output projection: logits[b,t,v] = h1seq[t*B+b,:] @ Wout + bout
    big_gemm<1><<<dim3(64, (VOCAB + 127) / 128), 256>>>(
        p_seq, Wout, VOCAB, bout, (float*)d_out, TSEQ*BATCH, VOCAB, HID);

    // 6) final states into tail of d_out (guarded by out_size)
    state_out<<<(BATCH*HID + 255) / 256, 256>>>((float*)d_out, (long long)out_size);
}

// round 2
// speedup vs baseline: 1.0497x; 1.0497x over previous
#include <cuda_runtime.h>
#include <math.h>

#define BATCH 128
#define TSEQ  64
#define VOCAB 10000
#define EMB   1024
#define HID   1024
#define NBLK  148
#define BH    (BATCH*HID)

typedef unsigned long long ull;

// ---------------- packed fp32x2 helpers (FFMA2 path) ----------------
__device__ __forceinline__ float2 up2(ull v) {
    float2 r; asm("mov.b64 {%0,%1}, %2;" : "=f"(r.x), "=f"(r.y) : "l"(v)); return r;
}
__device__ __forceinline__ ull fma2(ull a, ull b, ull c) {
    ull d; asm("fma.rn.f32x2 %0,%1,%2,%3;" : "=l"(d) : "l"(a), "l"(b), "l"(c)); return d;
}

// ---------------- device scratch ----------------
__device__ float g_x[TSEQ*BH];
__device__ float g_xu0[TSEQ*BH];
__device__ float g_xr0[TSEQ*BH];
__device__ float g_xc0[TSEQ*BH];
__device__ float g_h0buf[2*BH];
__device__ float g_h1buf[2*BH];
__device__ float g_u0[BH];
__device__ float g_rh0[BH];
__device__ float g_u1[BH];
__device__ float g_rh1[BH];
__device__ float g_h1seq[TSEQ*BH];
__device__ unsigned g_barcnt;
__device__ volatile unsigned g_barsense;

// ---------------- small kernels ----------------
__global__ void gather_kernel(const int* __restrict__ tok, const float* __restrict__ emb) {
    int row = blockIdx.x;                 // t*B + b
    int t = row >> 7, b = row & 127;
    int token = tok[b * TSEQ + t];
    const float4* src = (const float4*)(emb + (size_t)token * EMB);
    float4* dst = (float4*)(g_x + (size_t)row * EMB);
    dst[threadIdx.x] = src[threadIdx.x];
}

__global__ void init_h(const float* __restrict__ ihs) {
    int i = blockIdx.x * blockDim.x + threadIdx.x;
    if (i < BH) {
        g_h0buf[i] = ihs[i];
        g_h1buf[i] = ihs[BH + i];
    }
}

__global__ void state_out(float* __restrict__ out, long long out_size) {
    long long i = (long long)blockIdx.x * blockDim.x + threadIdx.x;
    long long base = (long long)BATCH * TSEQ * VOCAB;
    if (i < BH) {
        if (base + i < out_size)        out[base + i]      = g_h0buf[i];
        if (base + BH + i < out_size)   out[base + BH + i] = g_h1buf[i];
    }
}

// ---------------- big GEMM: C = A[M,K] @ W[K,N] + bias ----------------
// A stored duplicated in smem so FFMA2 operands come straight from LDS.128.
// MODE 0: C[m*N+n];  MODE 1: rows m = t*B+b remapped to C[(b*T+t)*N+n]
template<int MODE>
__global__ __launch_bounds__(256)
void big_gemm(const float* __restrict__ A, const float* __restrict__ W, int ldw,
              const float* __restrict__ bias, float* __restrict__ C,
              int M, int N, int K)
{
    __shared__ __align__(16) float As2[16 * 268];   // duplicated pairs, LD=268
    __shared__ __align__(16) float Bs [16 * 132];
    const int tid = threadIdx.x;
    const int tx = tid & 15, ty = tid >> 4;
    const int m0 = blockIdx.x * 128;
    const int n0 = blockIdx.y * 128;

    ull acc[8][4];
    #pragma unroll
    for (int i = 0; i < 8; ++i)
        #pragma unroll
        for (int j = 0; j < 4; ++j) acc[i][j] = 0ull;

    for (int k0 = 0; k0 < K; k0 += 16) {
        // A tile 128x16 -> duplicated-pair layout As2[k][2m],As2[k][2m+1]
        #pragma unroll
        for (int l = 0; l < 2; ++l) {
            int j = tid + l * 256;
            int m = j >> 2, kq = (j & 3) * 4;
            float4 v = *(const float4*)&A[(size_t)(m0 + m) * K + k0 + kq];
            *(float2*)&As2[(kq+0)*268 + 2*m] = make_float2(v.x, v.x);
            *(float2*)&As2[(kq+1)*268 + 2*m] = make_float2(v.y, v.y);
            *(float2*)&As2[(kq+2)*268 + 2*m] = make_float2(v.z, v.z);
            *(float2*)&As2[(kq+3)*268 + 2*m] = make_float2(v.w, v.w);
        }
        // W tile 16x128
        #pragma unroll
        for (int l = 0; l < 2; ++l) {
            int j = tid + l * 256;
            int kk = j >> 5, c = (j & 31) * 4;
            int n = n0 + c;
            const float* src = &W[(size_t)(k0 + kk) * ldw + n];
            float4 v;
            if (MODE == 0 || n + 3 < N) {
                v = *(const float4*)src;
            } else {
                v.x = (n   < N) ? src[0] : 0.f;
                v.y = (n+1 < N) ? src[1] : 0.f;
                v.z = (n+2 < N) ? src[2] : 0.f;
                v.w = 0.f;
            }
            *(float4*)&Bs[kk*132 + c] = v;
        }
        __syncthreads();
        #pragma unroll
        for (int kk = 0; kk < 16; ++kk) {
            ulonglong2 a0 = *(const ulonglong2*)&As2[kk*268 + ty*16 + 0];
            ulonglong2 a1 = *(const ulonglong2*)&As2[kk*268 + ty*16 + 4];
            ulonglong2 a2 = *(const ulonglong2*)&As2[kk*268 + ty*16 + 8];
            ulonglong2 a3 = *(const ulonglong2*)&As2[kk*268 + ty*16 + 12];
            ulonglong2 b0 = *(const ulonglong2*)&Bs[kk*132 + tx*8];
            ulonglong2 b1 = *(const ulonglong2*)&Bs[kk*132 + tx*8 + 4];
            ull ap[8] = {a0.x, a0.y, a1.x, a1.y, a2.x, a2.y, a3.x, a3.y};
            ull bp[4] = {b0.x, b0.y, b1.x, b1.y};
            #pragma unroll
            for (int i = 0; i < 8; ++i)
                #pragma unroll
                for (int j = 0; j < 4; ++j)
                    acc[i][j] = fma2(ap[i], bp[j], acc[i][j]);
        }
        __syncthreads();
    }
    #pragma unroll
    for (int i = 0; i < 8; ++i) {
        int m = m0 + ty * 8 + i;
        float* crow;
        if (MODE == 0) {
            crow = C + (size_t)m * N;
        } else {
            int b = m & 127, t = m >> 7;
            crow = C + ((size_t)b * TSEQ + t) * N;
        }
        #pragma unroll
        for (int j = 0; j < 4; ++j) {
            int n = n0 + tx * 8 + 2 * j;
            float2 p = up2(acc[i][j]);
            if (MODE == 0) {
                *(float2*)&crow[n] = make_float2(p.x + bias[n], p.y + bias[n + 1]);
            } else {
                if (n     < N) crow[n]     = p.x + bias[n];
                if (n + 1 < N) crow[n + 1] = p.y + bias[n + 1];
            }
        }
    }
}

// ---------------- persistent recurrence ----------------
struct RecParams {
    const float *wu0h, *wr0h, *wc0h;   // layer0 h-part weights [1024,1024]
    const float *wu1,  *wr1,  *wc1;    // layer1 weights [2048,1024]
    const float *bu1,  *br1,  *bc1;
    const float *xu, *xr, *xc;         // precomputed x-preacts (+bias), base ptrs
    float *h0, *h1;                    // ping-pong bases [2*BH]
    float *u0, *rh0, *u1, *rh1;
    float *seq;
};

struct PhaseDesc {
    const float* A1; const float* A2;  // A2 = second K-1024 half (layer1)
    const float* W;                    // [K,1024] row-major
    const float* add; int add_stride;  // preactivation addend (stride 0 => bias)
    const float* hprev; const float* u;
    float* out; float* out2;
    int mode;                          // 0: sigmoid  1: sigmoid*h  2: gru update
    int nchunk;                        // K/32
};

__device__ __forceinline__ void grid_barrier(unsigned& sense) {
    __syncthreads();
    if (threadIdx.x == 0) {
        unsigned next = sense ^ 1u;
        __threadfence();
        if (atomicAdd(&g_barcnt, 1u) == NBLK - 1) {
            g_barcnt = 0;
            __threadfence();
            g_barsense = next;
        } else {
            while (g_barsense != next) __nanosleep(32);
        }
    }
    sense ^= 1u;
    __syncthreads();
}

// tile: TM rows x 64 cols, 256 threads. Duplicated-pair A in smem.
template<int TM>
__device__ void tile_gemm(const PhaseDesc d, int m0, int n0, float* sm)
{
    constexpr int ASLD = 2 * TM + 4;        // 68 or 36 (keeps 16B row alignment)
    constexpr int BSLD = 68;
    float* As2 = sm;
    float* Bs  = sm + 32 * 68;
    const int tid = threadIdx.x;
    const int tx = tid & 15, ty = tid >> 4;
    constexpr int RPT = TM / 16;            // rows per thread (1 or 2)
    constexpr int ALOAD = (TM * 32) / 256;  // A elements per thread per chunk

    ull acc[RPT][2];
    #pragma unroll
    for (int r = 0; r < RPT; ++r) { acc[r][0] = 0ull; acc[r][1] = 0ull; }

    for (int c = 0; c < d.nchunk; ++c) {
        const float* Asrc = (c < 32) ? d.A1 : d.A2;
        int kl = (c & 31) * 32;
        int kg = c * 32;
        #pragma unroll
        for (int l = 0; l < ALOAD; ++l) {
            int i = tid + l * 256;
            int m = i >> 5, k = i & 31;
            float v = __ldcg(&Asrc[(size_t)(m0 + m) * HID + kl + k]);
            *(float2*)&As2[k * ASLD + 2 * m] = make_float2(v, v);
        }
        #pragma unroll
        for (int l = 0; l < 2; ++l) {
            int j = tid + l * 256;
            int kk = j >> 4, cc = (j & 15) * 4;
            float4 v = *(const float4*)&d.W[(size_t)(kg + kk) * HID + n0 + cc];
            *(float4*)&Bs[kk * BSLD + cc] = v;
        }
        __syncthreads();
        #pragma unroll
        for (int kk = 0; kk < 32; ++kk) {
            ulonglong2 b = *(const ulonglong2*)&Bs[kk * BSLD + tx * 4];
            if (RPT == 2) {
                ulonglong2 a = *(const ulonglong2*)&As2[kk * ASLD + ty * 4];
                acc[0][0] = fma2(a.x, b.x, acc[0][0]);
                acc[0][1] = fma2(a.x, b.y, acc[0][1]);
                acc[1][0] = fma2(a.y, b.x, acc[1][0]);
                acc[1][1] = fma2(a.y, b.y, acc[1][1]);
            } else {
                ull a = *(const ull*)&As2[kk * ASLD + ty * 2];
                acc[0][0] = fma2(a, b.x, acc[0][0]);
                acc[0][1] = fma2(a, b.y, acc[0][1]);
            }
        }
        __syncthreads();
    }
    #pragma unroll
    for (int r = 0; r < RPT; ++r) {
        int m = m0 + ty * RPT + r;
        #pragma unroll
        for (int j = 0; j < 2; ++j) {
            int n = n0 + tx * 4 + j * 2;
            size_t idx = (size_t)m * HID + n;
            float2 p = up2(acc[r][j]);
            float ax = d.add[(size_t)m * d.add_stride + n];
            float ay = d.add[(size_t)m * d.add_stride + n + 1];
            float px = p.x + ax, py = p.y + ay;
            if (d.mode == 0) {
                *(float2*)&d.out[idx] =
                    make_float2(1.f / (1.f + expf(-px)), 1.f / (1.f + expf(-py)));
            } else if (d.mode == 1) {
                float2 h = __ldcg((const float2*)&d.hprev[idx]);
                *(float2*)&d.out[idx] =
                    make_float2(h.x / (1.f + expf(-px)), h.y / (1.f + expf(-py)));
            } else {
                float2 h = __ldcg((const float2*)&d.hprev[idx]);
                float2 u = __ldcg((const float2*)&d.u[idx]);
                float cx = tanhf(px), cy = tanhf(py);
                float2 o = make_float2(u.x * h.x + (1.f - u.x) * cx,
                                       u.y * h.y + (1.f - u.y) * cy);
                *(float2*)&d.out[idx] = o;
                if (d.out2) *(float2*)&d.out2[idx] = o;
            }
        }
    }
}

__global__ __launch_bounds__(256, 1)
void recurrence_kernel(RecParams P)
{
    __shared__ __align__(16) float sm[32 * 68 + 32 * 68];
    unsigned sense = 0;
    const int bid = blockIdx.x;
    for (int t = 0; t < TSEQ; ++t) {
        const float* xu = P.xu + (size_t)t * BH;
        const float* xr = P.xr + (size_t)t * BH;
        const float* xc = P.xc + (size_t)t * BH;
        float* h0c = P.h0 + (size_t)(t & 1) * BH;
        float* h0n = P.h0 + (size_t)((t & 1) ^ 1) * BH;
        float* h1c = P.h1 + (size_t)(t & 1) * BH;
        float* h1n = P.h1 + (size_t)((t & 1) ^ 1) * BH;

        // Phase A: layer0 u,r gates — 128 tiles [32x64], K=1024
        if (bid < 128) {
            int g = bid >> 6, r = bid & 63;
            PhaseDesc d{h0c, nullptr, g ? P.wr0h : P.wu0h, g ? xr : xu, HID,
                        h0c, nullptr, g ? P.rh0 : P.u0, nullptr, g ? 1 : 0, 32};
            tile_gemm<32>(d, (r >> 4) * 32, (r & 15) * 64, sm);
        }
        grid_barrier(sense);
        // Phase B: layer0 candidate + update — 128 tiles [16x64], K=1024
        if (bid < 128) {
            PhaseDesc d{P.rh0, nullptr, P.wc0h, xc, HID, h0c, P.u0,
                        h0n, nullptr, 2, 32};
            tile_gemm<16>(d, (bid >> 4) * 16, (bid & 15) * 64, sm);
        }
        grid_barrier(sense);
        // Phase C: layer1 u,r gates — 128 tiles [32x64], K=2048 (A = [h0n | h1c])
        if (bid < 128) {
            int g = bid >> 6, r = bid & 63;
            PhaseDesc d{h0n, h1c, g ? P.wr1 : P.wu1, g ? P.br1 : P.bu1, 0,
                        h1c, nullptr, g ? P.rh1 : P.u1, nullptr, g ? 1 : 0, 64};
            tile_gemm<32>(d, (r >> 4) * 32, (r & 15) * 64, sm);
        }
        grid_barrier(sense);
        // Phase D: layer1 candidate + update — 128 tiles [16x64], K=2048
        if (bid < 128) {
            PhaseDesc d{h0n, P.rh1, P.wc1, P.bc1, 0, h1c, P.u1,
                        h1n, P.seq + (size_t)t * BH, 2, 64};
            tile_gemm<16>(d, (bid >> 4) * 16, (bid & 15) * 64, sm);
        }
        grid_barrier(sense);
    }
}

// ---------------- host orchestration ----------------
extern "C" void kernel_launch(void* const* d_in, const int* in_sizes, int n_in,
                              void* d_out, int out_size)
{
    const int*   tok  = (const int*)  d_in[0];
    const float* ihs  = (const float*)d_in[1];
    const float* emb  = (const float*)d_in[2];
    const float* Wout = (const float*)d_in[3];
    const float* bout = (const float*)d_in[4];
    const float* wu0  = (const float*)d_in[5];
    const float* bu0  = (const float*)d_in[6];
    const float* wr0  = (const float*)d_in[7];
    const float* br0  = (const float*)d_in[8];
    const float* wc0  = (const float*)d_in[9];
    const float* bc0  = (const float*)d_in[10];
    const float* wu1  = (const float*)d_in[11];
    const float* bu1  = (const float*)d_in[12];
    const float* wr1  = (const float*)d_in[13];
    const float* br1  = (const float*)d_in[14];
    const float* wc1  = (const float*)d_in[15];
    const float* bc1  = (const float*)d_in[16];

    float *p_x, *p_xu0, *p_xr0, *p_xc0, *p_h0, *p_h1;
    float *p_u0, *p_rh0, *p_u1, *p_rh1, *p_seq;
    cudaGetSymbolAddress((void**)&p_x,   g_x);
    cudaGetSymbolAddress((void**)&p_xu0, g_xu0);
    cudaGetSymbolAddress((void**)&p_xr0, g_xr0);
    cudaGetSymbolAddress((void**)&p_xc0, g_xc0);
    cudaGetSymbolAddress((void**)&p_h0,  g_h0buf);
    cudaGetSymbolAddress((void**)&p_h1,  g_h1buf);
    cudaGetSymbolAddress((void**)&p_u0,  g_u0);
    cudaGetSymbolAddress((void**)&p_rh0, g_rh0);
    cudaGetSymbolAddress((void**)&p_u1,  g_u1);
    cudaGetSymbolAddress((void**)&p_rh1, g_rh1);
    cudaGetSymbolAddress((void**)&p_seq, g_h1seq);

    // 1) gather embeddings
    gather_kernel<<<TSEQ * BATCH, 256>>>(tok, emb);

    // 2) precompute layer-0 x-projections (+bias)
    dim3 gpre(64, 8);
    big_gemm<0><<<gpre, 256>>>(p_x, wu0, HID, bu0, p_xu0, TSEQ*BATCH, HID, EMB);
    big_gemm<0><<<gpre, 256>>>(p_x, wr0, HID, br0, p_xr0, TSEQ*BATCH, HID, EMB);
    big_gemm<0><<<gpre, 256>>>(p_x, wc0, HID, bc0, p_xc0, TSEQ*BATCH, HID, EMB);

    // 3) initial hidden state
    init_h<<<(BH + 255) / 256, 256>>>(ihs);

    // 4) persistent recurrence (all 64 steps, device-wide barriers)
    RecParams P;
    P.wu0h = wu0 + (size_t)EMB * HID;
    P.wr0h = wr0 + (size_t)EMB * HID;
    P.wc0h = wc0 + (size_t)EMB * HID;
    P.wu1 = wu1; P.wr1 = wr1; P.wc1 = wc1;
    P.bu1 = bu1; P.br1 = br1; P.bc1 = bc1;
    P.xu = p_xu0; P.xr = p_xr0; P.xc = p_xc0;
    P.h0 = p_h0; P.h1 = p_h1;
    P.u0 = p_u0; P.rh0 = p_rh0; P.u1 = p_u1; P.rh1 = p_rh1;
    P.seq = p_seq;
    recurrence_kernel<<<NBLK, 256>>>(P);

    // 5) output projection: logits[b,t,v]
    big_gemm<1><<<dim3(64, (VOCAB + 127) / 128), 256>>>(
        p_seq, Wout, VOCAB, bout, (float*)d_out, TSEQ*BATCH, VOCAB, HID);

    // 6) final states
    state_out<<<(BH + 255) / 256, 256>>>((float*)d_out, (long long)out_size);
}

// round 3
// speedup vs baseline: 1.4070x; 1.3403x over previous
#include <cuda_runtime.h>
#include <math.h>

#define BATCH 128
#define TSEQ  64
#define VOCAB 10000
#define EMB   1024
#define HID   1024
#define NBLK  148
#define BH    (BATCH*HID)

typedef unsigned long long ull;

// ---------------- packed fp32x2 helpers ----------------
__device__ __forceinline__ ull pack2(float x, float y) {
    ull d; asm("mov.b64 %0, {%1, %2};" : "=l"(d) : "f"(x), "f"(y)); return d;
}
__device__ __forceinline__ float2 up2(ull v) {
    float2 r; asm("mov.b64 {%0,%1}, %2;" : "=f"(r.x), "=f"(r.y) : "l"(v)); return r;
}
__device__ __forceinline__ ull fma2(ull a, ull b, ull c) {
    ull d; asm("fma.rn.f32x2 %0,%1,%2,%3;" : "=l"(d) : "l"(a), "l"(b), "l"(c)); return d;
}
__device__ __forceinline__ float sigf(float x) { return 1.f / (1.f + expf(-x)); }

// ---------------- device scratch ----------------
__device__ float g_x[TSEQ*BH];
__device__ float g_xu0[TSEQ*BH];
__device__ float g_xr0[TSEQ*BH];
__device__ float g_xc0[TSEQ*BH];
__device__ float g_h0buf[2*BH];
__device__ float g_h1buf[2*BH];
__device__ float g_h1seq[TSEQ*BH];
__device__ float g_pA[4*128*2048];   // layer0 u|r partials  [ks][m][g*1024+n]
__device__ float g_pB[8*128*1024];   // layer0 c partials
__device__ float g_pC[4*128*2048];   // layer1 u|r partials
__device__ float g_pD[8*128*1024];   // layer1 c partials
__device__ unsigned g_barcnt;
__device__ volatile unsigned g_barsense;

// ---------------- small kernels ----------------
__global__ void gather_kernel(const int* __restrict__ tok, const float* __restrict__ emb) {
    int row = blockIdx.x;                 // t*B + b
    int t = row >> 7, b = row & 127;
    int token = tok[b * TSEQ + t];
    const float4* src = (const float4*)(emb + (size_t)token * EMB);
    float4* dst = (float4*)(g_x + (size_t)row * EMB);
    dst[threadIdx.x] = src[threadIdx.x];
}

__global__ void init_h(const float* __restrict__ ihs) {
    int i = blockIdx.x * blockDim.x + threadIdx.x;
    if (i < BH) {
        g_h0buf[i] = ihs[i];
        g_h1buf[i] = ihs[BH + i];
    }
}

__global__ void state_out(float* __restrict__ out, long long out_size) {
    long long i = (long long)blockIdx.x * blockDim.x + threadIdx.x;
    long long base = (long long)BATCH * TSEQ * VOCAB;
    if (i < BH) {
        if (base + i < out_size)      out[base + i]      = g_h0buf[i];
        if (base + BH + i < out_size) out[base + BH + i] = g_h1buf[i];
    }
}

// ---------------- big GEMM: C = A[M,K] @ W[K,N] + bias ----------------
// 128x128 tile, 128 threads, 16x8 per-thread register blocking.
// MODE 0: C[m*N+n];  MODE 1: rows m=t*B+b remapped to C[(b*T+t)*N+n], N guarded
template<int MODE>
__global__ __launch_bounds__(128, 2)
void big_gemm(const float* __restrict__ A, const float* __restrict__ W, int ldw,
              const float* __restrict__ bias, float* __restrict__ C,
              int M, int N, int K)
{
    __shared__ __align__(16) float As[16][132];
    __shared__ __align__(16) float Bs[16][132];
    const int tid = threadIdx.x;
    const int tx = tid & 15;        // n: 8 cols  (tx*8)
    const int ty = tid >> 4;        // m: 16 rows (ty*16)
    const int m0 = blockIdx.x * 128;
    const int n0 = blockIdx.y * 128;

    ull acc[16][4];
    #pragma unroll
    for (int i = 0; i < 16; ++i)
        #pragma unroll
        for (int j = 0; j < 4; ++j) acc[i][j] = 0ull;

    for (int k0 = 0; k0 < K; k0 += 16) {
        // A tile 128x16 -> As[k][m]
        #pragma unroll
        for (int l = 0; l < 4; ++l) {
            int i = tid + l * 128;
            int m = i >> 2, kq = (i & 3) * 4;
            float4 v = *(const float4*)&A[(size_t)(m0 + m) * K + k0 + kq];
            As[kq+0][m] = v.x; As[kq+1][m] = v.y; As[kq+2][m] = v.z; As[kq+3][m] = v.w;
        }
        // W tile 16x128
        #pragma unroll
        for (int l = 0; l < 4; ++l) {
            int i = tid + l * 128;
            int kk = i >> 5, c = (i & 31) * 4;
            int n = n0 + c;
            const float* src = &W[(size_t)(k0 + kk) * ldw + n];
            float4 v;
            if (MODE == 0 || n + 3 < N) {
                v = *(const float4*)src;
            } else {
                v.x = (n   < N) ? src[0] : 0.f;
                v.y = (n+1 < N) ? src[1] : 0.f;
                v.z = (n+2 < N) ? src[2] : 0.f;
                v.w = 0.f;
            }
            *(float4*)&Bs[kk][c] = v;
        }
        __syncthreads();
        #pragma unroll
        for (int kk = 0; kk < 16; ++kk) {
            float4 a0 = *(const float4*)&As[kk][ty*16 + 0];
            float4 a1 = *(const float4*)&As[kk][ty*16 + 4];
            float4 a2 = *(const float4*)&As[kk][ty*16 + 8];
            float4 a3 = *(const float4*)&As[kk][ty*16 + 12];
            ulonglong2 b0 = *(const ulonglong2*)&Bs[kk][tx*8];
            ulonglong2 b1 = *(const ulonglong2*)&Bs[kk][tx*8 + 4];
            ull bp[4] = {b0.x, b0.y, b1.x, b1.y};
            ull ad[16];
            ad[0]=pack2(a0.x,a0.x); ad[1]=pack2(a0.y,a0.y); ad[2]=pack2(a0.z,a0.z); ad[3]=pack2(a0.w,a0.w);
            ad[4]=pack2(a1.x,a1.x); ad[5]=pack2(a1.y,a1.y); ad[6]=pack2(a1.z,a1.z); ad[7]=pack2(a1.w,a1.w);
            ad[8]=pack2(a2.x,a2.x); ad[9]=pack2(a2.y,a2.y); ad[10]=pack2(a2.z,a2.z); ad[11]=pack2(a2.w,a2.w);
            ad[12]=pack2(a3.x,a3.x); ad[13]=pack2(a3.y,a3.y); ad[14]=pack2(a3.z,a3.z); ad[15]=pack2(a3.w,a3.w);
            #pragma unroll
            for (int i = 0; i < 16; ++i)
                #pragma unroll
                for (int j = 0; j < 4; ++j)
                    acc[i][j] = fma2(ad[i], bp[j], acc[i][j]);
        }
        __syncthreads();
    }
    #pragma unroll
    for (int i = 0; i < 16; ++i) {
        int m = m0 + ty * 16 + i;
        float* crow;
        if (MODE == 0) {
            crow = C + (size_t)m * N;
        } else {
            int b = m & 127, t = m >> 7;
            crow = C + ((size_t)b * TSEQ + t) * N;
        }
        #pragma unroll
        for (int j = 0; j < 4; ++j) {
            int n = n0 + tx * 8 + 2 * j;
            float2 p = up2(acc[i][j]);
            if (MODE == 0) {
                *(float2*)&crow[n] = make_float2(p.x + bias[n], p.y + bias[n+1]);
            } else {
                if (n     < N) crow[n]   = p.x + bias[n];
                if (n + 1 < N) crow[n+1] = p.y + bias[n+1];
            }
        }
    }
}

// ---------------- persistent recurrence ----------------
// Phase GEMM: [64x128] output tile, 128 threads, 8x8 per-thread, K-sliced.
// Writes fp32 partials; gate activations evaluated lazily by consumers.
struct GemmP {
    const float* W;         // weight base, already offset to this K-slice's rows
    const float* Asrc;      // plain A (lazy: the h to multiply by)
    const float* lazyPart;  // partial base at r-gate column offset (+1024); null = plain
    const float* lazyAdd;   // x-preact row base (stride HID) or bias (stride 0)
    int lazyAddStride;
    int koff;               // column offset into A rows
    int nchunks;            // K-slice / 16
    float* out;             // partial out base (ks and gate offsets folded in)
    int outW;               // 2048 or 1024
    int m0, n0;
};

__device__ __forceinline__ void rec_tile(const GemmP g, float* smem)
{
    float (*As)[68]  = (float(*)[68])smem;
    float (*Bs)[132] = (float(*)[132])(smem + 16 * 68);
    const int tid = threadIdx.x;
    const int tx = tid & 15;   // n: tx*8
    const int ty = tid >> 4;   // m: ty*8

    ull acc[8][4];
    #pragma unroll
    for (int i = 0; i < 8; ++i)
        #pragma unroll
        for (int j = 0; j < 4; ++j) acc[i][j] = 0ull;

    for (int c = 0; c < g.nchunks; ++c) {
        int kc = c * 16;
        // A tile 64x16 -> As[k][m]
        #pragma unroll
        for (int l = 0; l < 2; ++l) {
            int i = tid + l * 128;
            int m = i >> 2, kq = (i & 3) * 4;
            int mg = g.m0 + m;
            int kg = g.koff + kc + kq;
            if (g.lazyPart == nullptr) {
                float4 v = __ldcg((const float4*)&g.Asrc[(size_t)mg * HID + kg]);
                As[kq+0][m] = v.x; As[kq+1][m] = v.y; As[kq+2][m] = v.z; As[kq+3][m] = v.w;
            } else {
                #pragma unroll
                for (int q = 0; q < 4; ++q) {
                    int k = kg + q;
                    float s = g.lazyAdd[(size_t)mg * g.lazyAddStride + k];
                    #pragma unroll
                    for (int p = 0; p < 4; ++p)
                        s += __ldcg(&g.lazyPart[((size_t)p * 128 + mg) * 2048 + k]);
                    float h = __ldcg(&g.Asrc[(size_t)mg * HID + k]);
                    As[kq+q][m] = sigf(s) * h;
                }
            }
        }
        // W tile 16x128
        #pragma unroll
        for (int l = 0; l < 4; ++l) {
            int i = tid + l * 128;
            int kk = i >> 5, cc = (i & 31) * 4;
            float4 v = *(const float4*)&g.W[(size_t)(kc + kk) * HID + g.n0 + cc];
            *(float4*)&Bs[kk][cc] = v;
        }
        __syncthreads();
        #pragma unroll
        for (int kk = 0; kk < 16; ++kk) {
            float4 a0 = *(const float4*)&As[kk][ty*8 + 0];
            float4 a1 = *(const float4*)&As[kk][ty*8 + 4];
            ulonglong2 b0 = *(const ulonglong2*)&Bs[kk][tx*8];
            ulonglong2 b1 = *(const ulonglong2*)&Bs[kk][tx*8 + 4];
            ull bp[4] = {b0.x, b0.y, b1.x, b1.y};
            ull ad[8];
            ad[0]=pack2(a0.x,a0.x); ad[1]=pack2(a0.y,a0.y); ad[2]=pack2(a0.z,a0.z); ad[3]=pack2(a0.w,a0.w);
            ad[4]=pack2(a1.x,a1.x); ad[5]=pack2(a1.y,a1.y); ad[6]=pack2(a1.z,a1.z); ad[7]=pack2(a1.w,a1.w);
            #pragma unroll
            for (int i = 0; i < 8; ++i)
                #pragma unroll
                for (int j = 0; j < 4; ++j)
                    acc[i][j] = fma2(ad[i], bp[j], acc[i][j]);
        }
        __syncthreads();
    }
    #pragma unroll
    for (int i = 0; i < 8; ++i) {
        int m = g.m0 + ty * 8 + i;
        #pragma unroll
        for (int j = 0; j < 4; ++j) {
            int n = g.n0 + tx * 8 + 2 * j;
            float2 p = up2(acc[i][j]);
            *(float2*)&g.out[(size_t)m * g.outW + n] = p;
        }
    }
}

struct RecParams {
    const float *wu0h, *wr0h, *wc0h;   // layer0 h-part weights [1024,1024]
    const float *wu1,  *wr1,  *wc1;    // layer1 weights [2048,1024]
    const float *bu1,  *br1,  *bc1;
};

__device__ __forceinline__ void grid_barrier(unsigned& sense) {
    __syncthreads();
    if (threadIdx.x == 0) {
        unsigned next = sense ^ 1u;
        __threadfence();
        if (atomicAdd(&g_barcnt, 1u) == NBLK - 1) {
            g_barcnt = 0;
            __threadfence();
            g_barsense = next;
        } else {
            while (g_barsense != next) __nanosleep(32);
        }
    }
    sense ^= 1u;
    __syncthreads();
}

__global__ __launch_bounds__(128, 1)
void recurrence_kernel(RecParams P)
{
    __shared__ __align__(16) float smem[16*68 + 16*132];
    unsigned sense = 0;
    const int bid = blockIdx.x;
    const int tid = threadIdx.x;

    for (int t = 0; t < TSEQ; ++t) {
        const float* xu = g_xu0 + (size_t)t * BH;
        const float* xr = g_xr0 + (size_t)t * BH;
        const float* xc = g_xc0 + (size_t)t * BH;
        float* h0c = g_h0buf + (size_t)(t & 1) * BH;
        float* h0n = g_h0buf + (size_t)((t & 1) ^ 1) * BH;
        float* h1c = g_h1buf + (size_t)(t & 1) * BH;
        float* h1n = g_h1buf + (size_t)((t & 1) ^ 1) * BH;

        // ---- Phase A: layer0 u,r h-part GEMM -> pA (K-split x4) ----
        if (bid < 128) {
            int ks = bid & 3, nt = (bid >> 2) & 7, mt = (bid >> 5) & 1, gg = bid >> 6;
            GemmP g;
            g.W = (gg ? P.wr0h : P.wu0h) + (size_t)ks * 256 * HID;
            g.Asrc = h0c; g.lazyPart = nullptr; g.lazyAdd = nullptr; g.lazyAddStride = 0;
            g.koff = ks * 256; g.nchunks = 16;
            g.out = g_pA + (size_t)ks * 128 * 2048 + gg * 1024;
            g.outW = 2048; g.m0 = mt * 64; g.n0 = nt * 128;
            rec_tile(g, smem);
        }
        grid_barrier(sense);

        // ---- Phase B: layer0 candidate GEMM (A = rh0 lazy) -> pB (x8) ----
        if (bid < 128) {
            int ks = bid & 7, nt = (bid >> 3) & 7, mt = (bid >> 6) & 1;
            GemmP g;
            g.W = P.wc0h + (size_t)ks * 128 * HID;
            g.Asrc = h0c; g.lazyPart = g_pA + 1024; g.lazyAdd = xr; g.lazyAddStride = HID;
            g.koff = ks * 128; g.nchunks = 8;
            g.out = g_pB + (size_t)ks * 128 * 1024;
            g.outW = 1024; g.m0 = mt * 64; g.n0 = nt * 128;
            rec_tile(g, smem);
        }
        grid_barrier(sense);

        // ---- ACT B: h0n = u0*h0c + (1-u0)*tanh(sum pB + xc) ----
        for (int i = bid * 128 + tid; i < BH / 2; i += NBLK * 128) {
            int m = (i * 2) >> 10, n = (i * 2) & 1023;
            float2 su = make_float2(xu[m * HID + n], xu[m * HID + n + 1]);
            #pragma unroll
            for (int p = 0; p < 4; ++p) {
                float2 v = __ldcg((const float2*)&g_pA[((size_t)p * 128 + m) * 2048 + n]);
                su.x += v.x; su.y += v.y;
            }
            float2 sc = make_float2(xc[m * HID + n], xc[m * HID + n + 1]);
            #pragma unroll
            for (int p = 0; p < 8; ++p) {
                float2 v = __ldcg((const float2*)&g_pB[((size_t)p * 128 + m) * 1024 + n]);
                sc.x += v.x; sc.y += v.y;
            }
            float2 h = __ldcg((const float2*)&h0c[m * HID + n]);
            float ux = sigf(su.x), uy = sigf(su.y);
            float cx = tanhf(sc.x), cy = tanhf(sc.y);
            *(float2*)&h0n[m * HID + n] =
                make_float2(ux * h.x + (1.f - ux) * cx, uy * h.y + (1.f - uy) * cy);
        }
        grid_barrier(sense);

        // ---- Phase C: layer1 u,r GEMM, K=2048 over [h0n | h1c] -> pC (x4) ----
        if (bid < 128) {
            int ks = bid & 3, nt = (bid >> 2) & 7, mt = (bid >> 5) & 1, gg = bid >> 6;
            GemmP g;
            g.W = (gg ? P.wr1 : P.wu1) + (size_t)ks * 512 * HID;
            g.Asrc = (ks < 2) ? h0n : h1c;
            g.lazyPart = nullptr; g.lazyAdd = nullptr; g.lazyAddStride = 0;
            g.koff = (ks & 1) * 512; g.nchunks = 32;
            g.out = g_pC + (size_t)ks * 128 * 2048 + gg * 1024;
            g.outW = 2048; g.m0 = mt * 64; g.n0 = nt * 128;
            rec_tile(g, smem);
        }
        grid_barrier(sense);

        // ---- Phase D: layer1 candidate GEMM over [h0n | rh1(lazy)] -> pD (x8) ----
        if (bid < 128) {
            int ks = bid & 7, nt = (bid >> 3) & 7, mt = (bid >> 6) & 1;
            GemmP g;
            g.W = P.wc1 + (size_t)ks * 256 * HID;
            if (ks < 4) {
                g.Asrc = h0n; g.lazyPart = nullptr; g.lazyAdd = nullptr; g.lazyAddStride = 0;
                g.koff = ks * 256;
            } else {
                g.Asrc = h1c; g.lazyPart = g_pC + 1024; g.lazyAdd = P.br1; g.lazyAddStride = 0;
                g.koff = (ks - 4) * 256;
            }
            g.nchunks = 16;
            g.out = g_pD + (size_t)ks * 128 * 1024;
            g.outW = 1024; g.m0 = mt * 64; g.n0 = nt * 128;
            rec_tile(g, smem);
        }
        grid_barrier(sense);

        // ---- ACT D: h1n = u1*h1c + (1-u1)*tanh(sum pD + bc1); also h1seq ----
        {
            float* seq = g_h1seq + (size_t)t * BH;
            for (int i = bid * 128 + tid; i < BH / 2; i += NBLK * 128) {
                int m = (i * 2) >> 10, n = (i * 2) & 1023;
                float2 su = make_float2(P.bu1[n], P.bu1[n + 1]);
                #pragma unroll
                for (int p = 0; p < 4; ++p) {
                    float2 v = __ldcg((const float2*)&g_pC[((size_t)p * 128 + m) * 2048 + n]);
                    su.x += v.x; su.y += v.y;
                }
                float2 sc = make_float2(P.bc1[n], P.bc1[n + 1]);
                #pragma unroll
                for (int p = 0; p < 8; ++p) {
                    float2 v = __ldcg((const float2*)&g_pD[((size_t)p * 128 + m) * 1024 + n]);
                    sc.x += v.x; sc.y += v.y;
                }
                float2 h = __ldcg((const float2*)&h1c[m * HID + n]);
                float ux = sigf(su.x), uy = sigf(su.y);
                float cx = tanhf(sc.x), cy = tanhf(sc.y);
                float2 o = make_float2(ux * h.x + (1.f - ux) * cx,
                                       uy * h.y + (1.f - uy) * cy);
                *(float2*)&h1n[m * HID + n] = o;
                *(float2*)&seq[m * HID + n] = o;
            }
        }
        grid_barrier(sense);
    }
}

// ---------------- host orchestration ----------------
extern "C" void kernel_launch(void* const* d_in, const int* in_sizes, int n_in,
                              void* d_out, int out_size)
{
    const int*   tok  = (const int*)  d_in[0];
    const float* ihs  = (const float*)d_in[1];
    const float* emb  = (const float*)d_in[2];
    const float* Wout = (const float*)d_in[3];
    const float* bout = (const float*)d_in[4];
    const float* wu0  = (const float*)d_in[5];
    const float* bu0  = (const float*)d_in[6];
    const float* wr0  = (const float*)d_in[7];
    const float* br0  = (const float*)d_in[8];
    const float* wc0  = (const float*)d_in[9];
    const float* bc0  = (const float*)d_in[10];
    const float* wu1  = (const float*)d_in[11];
    const float* bu1  = (const float*)d_in[12];
    const float* wr1  = (const float*)d_in[13];
    const float* br1  = (const float*)d_in[14];
    const float* wc1  = (const float*)d_in[15];
    const float* bc1  = (const float*)d_in[16];

    float *p_x, *p_xu0, *p_xr0, *p_xc0, *p_seq;
    cudaGetSymbolAddress((void**)&p_x,   g_x);
    cudaGetSymbolAddress((void**)&p_xu0, g_xu0);
    cudaGetSymbolAddress((void**)&p_xr0, g_xr0);
    cudaGetSymbolAddress((void**)&p_xc0, g_xc0);
    cudaGetSymbolAddress((void**)&p_seq, g_h1seq);

    // 1) gather embeddings
    gather_kernel<<<TSEQ * BATCH, 256>>>(tok, emb);

    // 2) precompute layer-0 x-projections (+bias)
    dim3 gpre(64, 8);
    big_gemm<0><<<gpre, 128>>>(p_x, wu0, HID, bu0, p_xu0, TSEQ*BATCH, HID, EMB);
    big_gemm<0><<<gpre, 128>>>(p_x, wr0, HID, br0, p_xr0, TSEQ*BATCH, HID, EMB);
    big_gemm<0><<<gpre, 128>>>(p_x, wc0, HID, bc0, p_xc0, TSEQ*BATCH, HID, EMB);

    // 3) initial hidden state
    init_h<<<(BH + 255) / 256, 256>>>(ihs);

    // 4) persistent recurrence
    RecParams P;
    P.wu0h = wu0 + (size_t)EMB * HID;
    P.wr0h = wr0 + (size_t)EMB * HID;
    P.wc0h = wc0 + (size_t)EMB * HID;
    P.wu1 = wu1; P.wr1 = wr1; P.wc1 = wc1;
    P.bu1 = bu1; P.br1 = br1; P.bc1 = bc1;
    recurrence_kernel<<<NBLK, 128>>>(P);

    // 5) output projection: logits[b,t,v]
    big_gemm<1><<<dim3(64, (VOCAB + 127) / 128), 128>>>(
        p_seq, Wout, VOCAB, bout, (float*)d_out, TSEQ*BATCH, VOCAB, HID);

    // 6) final states
    state_out<<<(BH + 255) / 256, 256>>>((float*)d_out, (long long)out_size);
}

// round 5
// speedup vs baseline: 2.1183x; 1.5055x over previous
#include <cuda_runtime.h>
#include <cuda_bf16.h>
#include <math.h>

#define BATCH 128
#define TSEQ  64
#define VOCAB 10000
#define EMB   1024
#define HID   1024
#define NBLK  148
#define BH    (BATCH*HID)
#define NPAD  10240          // VOCAB padded to 128

typedef unsigned long long ull;

// ---------------- packed fp32x2 helpers ----------------
__device__ __forceinline__ ull pack2(float x, float y) {
    ull d; asm("mov.b64 %0, {%1, %2};" : "=l"(d) : "f"(x), "f"(y)); return d;
}
__device__ __forceinline__ float2 up2(ull v) {
    float2 r; asm("mov.b64 {%0,%1}, %2;" : "=f"(r.x), "=f"(r.y) : "l"(v)); return r;
}
__device__ __forceinline__ ull fma2(ull a, ull b, ull c) {
    ull d; asm("fma.rn.f32x2 %0,%1,%2,%3;" : "=l"(d) : "l"(a), "l"(b), "l"(c)); return d;
}
__device__ __forceinline__ float sigf(float x) { return 1.f / (1.f + expf(-x)); }

// ---------------- mma.sync helpers (arch-agnostic tensor path) ----------------
__device__ __forceinline__ unsigned smem_u32(const void* p) {
    unsigned a;
    asm("{ .reg .u64 t; cvta.to.shared.u64 t, %1; cvt.u32.u64 %0, t; }" : "=r"(a) : "l"(p));
    return a;
}
__device__ __forceinline__ void ldsm4(unsigned* r, unsigned a) {
    asm volatile("ldmatrix.sync.aligned.m8n8.x4.shared.b16 {%0,%1,%2,%3}, [%4];"
                 : "=r"(r[0]), "=r"(r[1]), "=r"(r[2]), "=r"(r[3]) : "r"(a));
}
__device__ __forceinline__ void mma16816(float* c, const unsigned* a, unsigned b0, unsigned b1) {
    asm volatile("mma.sync.aligned.m16n8k16.row.col.f32.bf16.bf16.f32 "
                 "{%0,%1,%2,%3}, {%4,%5,%6,%7}, {%8,%9}, {%0,%1,%2,%3};"
                 : "+f"(c[0]), "+f"(c[1]), "+f"(c[2]), "+f"(c[3])
                 : "r"(a[0]), "r"(a[1]), "r"(a[2]), "r"(a[3]), "r"(b0), "r"(b1));
}
__device__ __forceinline__ void cpa16(unsigned saddr, const void* g) {
    asm volatile("cp.async.ca.shared.global [%0], [%1], 16;" :: "r"(saddr), "l"(g));
}

// ---------------- device scratch ----------------
__device__ float g_x[TSEQ*BH];
__device__ float g_xu0[TSEQ*BH];
__device__ float g_xr0[TSEQ*BH];
__device__ float g_xc0[TSEQ*BH];
__device__ float g_h0buf[2*BH];
__device__ float g_h1buf[2*BH];
__device__ float g_h1seq[TSEQ*BH];
__device__ float g_pA[4*128*2048];
__device__ float g_pB[8*128*1024];
__device__ float g_pC[4*128*2048];
__device__ float g_pD[8*128*1024];
__device__ __nv_bfloat16 g_ah[TSEQ*BH];       // A hi
__device__ __nv_bfloat16 g_al[TSEQ*BH];       // A lo
__device__ __nv_bfloat16 g_bth[NPAD*1024];    // W^T hi  [N][K]
__device__ __nv_bfloat16 g_btl[NPAD*1024];    // W^T lo
__device__ unsigned g_barcnt;
__device__ volatile unsigned g_barsense;

// ---------------- small kernels ----------------
__global__ void gather_kernel(const int* __restrict__ tok, const float* __restrict__ emb) {
    int row = blockIdx.x;                 // t*B + b
    int t = row >> 7, b = row & 127;
    int token = tok[b * TSEQ + t];
    const float4* src = (const float4*)(emb + (size_t)token * EMB);
    float4* dst = (float4*)(g_x + (size_t)row * EMB);
    dst[threadIdx.x] = src[threadIdx.x];
}

__global__ void init_h(const float* __restrict__ ihs) {
    int i = blockIdx.x * blockDim.x + threadIdx.x;
    if (i < BH) {
        g_h0buf[i] = ihs[i];
        g_h1buf[i] = ihs[BH + i];
    }
}

__global__ void state_out(float* __restrict__ out, long long out_size) {
    long long i = (long long)blockIdx.x * blockDim.x + threadIdx.x;
    long long base = (long long)BATCH * TSEQ * VOCAB;
    if (i < BH) {
        if (base + i < out_size)      out[base + i]      = g_h0buf[i];
        if (base + BH + i < out_size) out[base + BH + i] = g_h1buf[i];
    }
}

// fp32 -> bf16 hi/lo split
__global__ void cvt_split(const float* __restrict__ src,
                          __nv_bfloat16* __restrict__ oh, __nv_bfloat16* __restrict__ ol,
                          int n4) {
    int i = blockIdx.x * blockDim.x + threadIdx.x;
    if (i >= n4) return;
    float4 v = ((const float4*)src)[i];
    __nv_bfloat16 h0 = __float2bfloat16(v.x), h1 = __float2bfloat16(v.y);
    __nv_bfloat16 h2 = __float2bfloat16(v.z), h3 = __float2bfloat16(v.w);
    __nv_bfloat16 l0 = __float2bfloat16(v.x - __bfloat162float(h0));
    __nv_bfloat16 l1 = __float2bfloat16(v.y - __bfloat162float(h1));
    __nv_bfloat16 l2 = __float2bfloat16(v.z - __bfloat162float(h2));
    __nv_bfloat16 l3 = __float2bfloat16(v.w - __bfloat162float(h3));
    ((__nv_bfloat162*)oh)[2*i]   = __halves2bfloat162(h0, h1);
    ((__nv_bfloat162*)oh)[2*i+1] = __halves2bfloat162(h2, h3);
    ((__nv_bfloat162*)ol)[2*i]   = __halves2bfloat162(l0, l1);
    ((__nv_bfloat162*)ol)[2*i+1] = __halves2bfloat162(l2, l3);
}

// transpose + hi/lo convert: W[k][n] (ldw) -> Wt_h/Wt_l [n][k], K=1024, zero-pad n>=N
__global__ void tconv(const float* __restrict__ W, int ldw, int N,
                      __nv_bfloat16* __restrict__ th, __nv_bfloat16* __restrict__ tl) {
    __shared__ float t[32][33];
    int n0 = blockIdx.x * 32, k0 = blockIdx.y * 32;
    int tx = threadIdx.x, ty = threadIdx.y;   // 32 x 8
    #pragma unroll
    for (int r = 0; r < 4; ++r) {
        int k = k0 + ty + r * 8, n = n0 + tx;
        t[ty + r * 8][tx] = (n < N) ? W[(size_t)k * ldw + n] : 0.f;
    }
    __syncthreads();
    #pragma unroll
    for (int r = 0; r < 4; ++r) {
        int n = n0 + ty + r * 8, k = k0 + tx;
        float x = t[tx][ty + r * 8];
        __nv_bfloat16 hh = __float2bfloat16(x);
        __nv_bfloat16 ll = __float2bfloat16(x - __bfloat162float(hh));
        th[(size_t)n * 1024 + k] = hh;
        tl[(size_t)n * 1024 + k] = ll;
    }
}

// ---------------- mma.sync bf16-split GEMM ----------------
// C[128x128 per CTA] = (Ah+Al)[8192x1024] @ (Bh+Bl)^T + bias, fp32 accum.
// 8 warps (2m x 4n), warp tile 64x32, K chunks of 32 double-buffered via cp.async.
// MODE 0: C[m*N+n];  MODE 1: rows m=t*B+b -> C[(b*T+t)*N+n], guarded by N.
#define MM_LD 40                 // smem row stride (bf16)
#define MM_MS (128*MM_LD)        // one matrix tile (elems)
#define MM_STG (4*MM_MS)         // stage stride (elems)

template<int MODE>
__global__ __launch_bounds__(256, 1)
void mma_gemm(const __nv_bfloat16* __restrict__ Ah, const __nv_bfloat16* __restrict__ Al,
              const __nv_bfloat16* __restrict__ Bh, const __nv_bfloat16* __restrict__ Bl,
              const float* __restrict__ bias, float* __restrict__ C, int N)
{
    extern __shared__ __align__(16) __nv_bfloat16 sm[];
    const int tid = threadIdx.x, w = tid >> 5, l = tid & 31;
    const int m0 = blockIdx.x * 128, n0 = blockIdx.y * 128;
    const int mw = (w >> 2) * 64, nw = (w & 3) * 32;
    const unsigned sbase = smem_u32(sm);

    float acc[4][4][4];
    #pragma unroll
    for (int i = 0; i < 4; ++i)
        #pragma unroll
        for (int j = 0; j < 4; ++j)
            #pragma unroll
            for (int q = 0; q < 4; ++q) acc[i][j][q] = 0.f;

    // stage loader: 4 matrices x (128 rows x 32 cols) bf16, 2x uint4 per thread each
    auto stage_load = [&](int c, int s) {
        int kc = c * 32;
        unsigned sb = sbase + (unsigned)(s * MM_STG) * 2;
        #pragma unroll
        for (int l2 = 0; l2 < 2; ++l2) {
            int u = tid + l2 * 256;          // 512 units
            int row = u >> 2, q = u & 3;
            unsigned soff = (unsigned)(row * MM_LD + q * 8) * 2;
            size_t ga = (size_t)(m0 + row) * 1024 + kc + q * 8;
            size_t gb = (size_t)(n0 + row) * 1024 + kc + q * 8;
            cpa16(sb + 0 * MM_MS * 2 + soff, Ah + ga);
            cpa16(sb + 1 * MM_MS * 2 + soff, Al + ga);
            cpa16(sb + 2 * MM_MS * 2 + soff, Bh + gb);
            cpa16(sb + 3 * MM_MS * 2 + soff, Bl + gb);
        }
    };

    stage_load(0, 0);
    asm volatile("cp.async.commit_group;" ::: "memory");

    const int ldrow = ((l >> 3) & 1) * 8 + (l & 7);   // ldmatrix row-in-tile
    const int ldcol = (l >> 4) * 8;                    // ldmatrix col offset

    for (int c = 0; c < 32; ++c) {
        if (c + 1 < 32) {
            stage_load(c + 1, (c + 1) & 1);
            asm volatile("cp.async.commit_group;" ::: "memory");
            asm volatile("cp.async.wait_group 1;" ::: "memory");
        } else {
            asm volatile("cp.async.wait_group 0;" ::: "memory");
        }
        __syncthreads();

        unsigned sb = sbase + (unsigned)((c & 1) * MM_STG) * 2;
        #pragma unroll
        for (int kk = 0; kk < 2; ++kk) {
            unsigned aH[4][4], aL[4][4], bH[4][2], bL[4][2];
            #pragma unroll
            for (int mt = 0; mt < 4; ++mt) {
                int r = mw + mt * 16 + ldrow;
                unsigned ad = sb + (unsigned)(r * MM_LD + kk * 16 + ldcol) * 2;
                ldsm4(aH[mt], ad);
                ldsm4(aL[mt], ad + MM_MS * 2);
            }
            #pragma unroll
            for (int p = 0; p < 2; ++p) {
                int r = nw + p * 16 + ldrow;
                unsigned bd = sb + (unsigned)(2 * MM_MS + r * MM_LD + kk * 16 + ldcol) * 2;
                unsigned t0[4], t1[4];
                ldsm4(t0, bd);
                ldsm4(t1, bd + MM_MS * 2);
                bH[2*p][0] = t0[0]; bH[2*p][1] = t0[2];
                bH[2*p+1][0] = t0[1]; bH[2*p+1][1] = t0[3];
                bL[2*p][0] = t1[0]; bL[2*p][1] = t1[2];
                bL[2*p+1][0] = t1[1]; bL[2*p+1][1] = t1[3];
            }
            #pragma unroll
            for (int mt = 0; mt < 4; ++mt)
                #pragma unroll
                for (int nt = 0; nt < 4; ++nt) {
                    mma16816(acc[mt][nt], aH[mt], bH[nt][0], bH[nt][1]);
                    mma16816(acc[mt][nt], aH[mt], bL[nt][0], bL[nt][1]);
                    mma16816(acc[mt][nt], aL[mt], bH[nt][0], bH[nt][1]);
                }
        }
        __syncthreads();
    }

    // epilogue
    int g = l >> 2, tg = l & 3;
    #pragma unroll
    for (int mt = 0; mt < 4; ++mt) {
        int r0 = m0 + mw + mt * 16 + g;
        int r1 = r0 + 8;
        float *crow0, *crow1;
        if (MODE == 0) {
            crow0 = C + (size_t)r0 * N;
            crow1 = C + (size_t)r1 * N;
        } else {
            crow0 = C + ((size_t)(r0 & 127) * TSEQ + (r0 >> 7)) * N;
            crow1 = C + ((size_t)(r1 & 127) * TSEQ + (r1 >> 7)) * N;
        }
        #pragma unroll
        for (int nt = 0; nt < 4; ++nt) {
            int n = n0 + nw + nt * 8 + tg * 2;
            if (MODE == 0 || n < N) {
                float2 bv = *(const float2*)&bias[n];
                *(float2*)&crow0[n] = make_float2(acc[mt][nt][0] + bv.x, acc[mt][nt][1] + bv.y);
                *(float2*)&crow1[n] = make_float2(acc[mt][nt][2] + bv.x, acc[mt][nt][3] + bv.y);
            }
        }
    }
}

// ---------------- persistent recurrence (SIMT fp32, 256 threads/CTA) ----------------
struct GemmP {
    const float* W;
    const float* Asrc;
    const float* lazyPart;
    const float* lazyAdd;
    int lazyAddStride;
    int koff;
    int nchunks;
    float* out;
    int outW;
    int m0, n0;
};

__device__ __forceinline__ void rec_tile(const GemmP g, float* smemf)
{
    float (*As)[68]  = (float(*)[68])smemf;
    float (*Bs)[132] = (float(*)[132])(smemf + 16 * 68);
    const int tid = threadIdx.x;
    const int tx = tid & 31;   // n = tx*4
    const int ty = tid >> 5;   // m = ty*8

    ull acc[8][2];
    #pragma unroll
    for (int i = 0; i < 8; ++i) { acc[i][0] = 0ull; acc[i][1] = 0ull; }

    for (int c = 0; c < g.nchunks; ++c) {
        int kc = c * 16;
        {
            int m = tid >> 2, kq = (tid & 3) * 4;
            int mg = g.m0 + m;
            int kg = g.koff + kc + kq;
            if (g.lazyPart == nullptr) {
                float4 v = __ldcg((const float4*)&g.Asrc[(size_t)mg * HID + kg]);
                As[kq+0][m] = v.x; As[kq+1][m] = v.y; As[kq+2][m] = v.z; As[kq+3][m] = v.w;
            } else {
                #pragma unroll
                for (int q = 0; q < 4; ++q) {
                    int k = kg + q;
                    float s = g.lazyAdd[(size_t)mg * g.lazyAddStride + k];
                    #pragma unroll
                    for (int p = 0; p < 4; ++p)
                        s += __ldcg(&g.lazyPart[((size_t)p * 128 + mg) * 2048 + k]);
                    float h = __ldcg(&g.Asrc[(size_t)mg * HID + k]);
                    As[kq+q][m] = sigf(s) * h;
                }
            }
        }
        #pragma unroll
        for (int l = 0; l < 2; ++l) {
            int i = tid + l * 256;
            int kk = i >> 5, cc = (i & 31) * 4;
            float4 v = *(const float4*)&g.W[(size_t)(kc + kk) * HID + g.n0 + cc];
            *(float4*)&Bs[kk][cc] = v;
        }
        __syncthreads();
        #pragma unroll
        for (int kk = 0; kk < 16; ++kk) {
            float4 a0 = *(const float4*)&As[kk][ty*8 + 0];
            float4 a1 = *(const float4*)&As[kk][ty*8 + 4];
            ulonglong2 b = *(const ulonglong2*)&Bs[kk][tx*4];
            ull ad[8];
            ad[0]=pack2(a0.x,a0.x); ad[1]=pack2(a0.y,a0.y); ad[2]=pack2(a0.z,a0.z); ad[3]=pack2(a0.w,a0.w);
            ad[4]=pack2(a1.x,a1.x); ad[5]=pack2(a1.y,a1.y); ad[6]=pack2(a1.z,a1.z); ad[7]=pack2(a1.w,a1.w);
            #pragma unroll
            for (int i = 0; i < 8; ++i) {
                acc[i][0] = fma2(ad[i], b.x, acc[i][0]);
                acc[i][1] = fma2(ad[i], b.y, acc[i][1]);
            }
        }
        __syncthreads();
    }
    #pragma unroll
    for (int i = 0; i < 8; ++i) {
        int m = g.m0 + ty * 8 + i;
        #pragma unroll
        for (int j = 0; j < 2; ++j) {
            int n = g.n0 + tx * 4 + 2 * j;
            *(float2*)&g.out[(size_t)m * g.outW + n] = up2(acc[i][j]);
        }
    }
}

struct RecParams {
    const float *wu0h, *wr0h, *wc0h;
    const float *wu1,  *wr1,  *wc1;
    const float *bu1,  *br1,  *bc1;
};

__device__ __forceinline__ void grid_barrier(unsigned& sense) {
    __syncthreads();
    if (threadIdx.x == 0) {
        unsigned next = sense ^ 1u;
        __threadfence();
        if (atomicAdd(&g_barcnt, 1u) == NBLK - 1) {
            g_barcnt = 0;
            __threadfence();
            g_barsense = next;
        } else {
            while (g_barsense != next) __nanosleep(32);
        }
    }
    sense ^= 1u;
    __syncthreads();
}

__global__ __launch_bounds__(256, 1)
void recurrence_kernel(RecParams P)
{
    __shared__ __align__(16) float smemf[16*68 + 16*132];
    unsigned sense = 0;
    const int bid = blockIdx.x;
    const int tid = threadIdx.x;

    for (int t = 0; t < TSEQ; ++t) {
        const float* xu = g_xu0 + (size_t)t * BH;
        const float* xr = g_xr0 + (size_t)t * BH;
        const float* xc = g_xc0 + (size_t)t * BH;
        float* h0c = g_h0buf + (size_t)(t & 1) * BH;
        float* h0n = g_h0buf + (size_t)((t & 1) ^ 1) * BH;
        float* h1c = g_h1buf + (size_t)(t & 1) * BH;
        float* h1n = g_h1buf + (size_t)((t & 1) ^ 1) * BH;

        // Phase A: layer0 u,r h-part -> pA (K-split x4)
        if (bid < 128) {
            int ks = bid & 3, nt = (bid >> 2) & 7, mt = (bid >> 5) & 1, gg = bid >> 6;
            GemmP g;
            g.W = (gg ? P.wr0h : P.wu0h) + (size_t)ks * 256 * HID;
            g.Asrc = h0c; g.lazyPart = nullptr; g.lazyAdd = nullptr; g.lazyAddStride = 0;
            g.koff = ks * 256; g.nchunks = 16;
            g.out = g_pA + (size_t)ks * 128 * 2048 + gg * 1024;
            g.outW = 2048; g.m0 = mt * 64; g.n0 = nt * 128;
            rec_tile(g, smemf);
        }
        grid_barrier(sense);

        // Phase B: layer0 candidate (A = rh0 lazy) -> pB (x8)
        if (bid < 128) {
            int ks = bid & 7, nt = (bid >> 3) & 7, mt = (bid >> 6) & 1;
            GemmP g;
            g.W = P.wc0h + (size_t)ks * 128 * HID;
            g.Asrc = h0c; g.lazyPart = g_pA + 1024; g.lazyAdd = xr; g.lazyAddStride = HID;
            g.koff = ks * 128; g.nchunks = 8;
            g.out = g_pB + (size_t)ks * 128 * 1024;
            g.outW = 1024; g.m0 = mt * 64; g.n0 = nt * 128;
            rec_tile(g, smemf);
        }
        grid_barrier(sense);

        // ACT B
        for (int i = bid * 256 + tid; i < BH / 2; i += NBLK * 256) {
            int m = (i * 2) >> 10, n = (i * 2) & 1023;
            float2 su = make_float2(xu[m * HID + n], xu[m * HID + n + 1]);
            #pragma unroll
            for (int p = 0; p < 4; ++p) {
                float2 v = __ldcg((const float2*)&g_pA[((size_t)p * 128 + m) * 2048 + n]);
                su.x += v.x; su.y += v.y;
            }
            float2 sc = make_float2(xc[m * HID + n], xc[m * HID + n + 1]);
            #pragma unroll
            for (int p = 0; p < 8; ++p) {
                float2 v = __ldcg((const float2*)&g_pB[((size_t)p * 128 + m) * 1024 + n]);
                sc.x += v.x; sc.y += v.y;
            }
            float2 h = __ldcg((const float2*)&h0c[m * HID + n]);
            float ux = sigf(su.x), uy = sigf(su.y);
            float cx = tanhf(sc.x), cy = tanhf(sc.y);
            *(float2*)&h0n[m * HID + n] =
                make_float2(ux * h.x + (1.f - ux) * cx, uy * h.y + (1.f - uy) * cy);
        }
        grid_barrier(sense);

        // Phase C: layer1 u,r over [h0n | h1c] -> pC (x4)
        if (bid < 128) {
            int ks = bid & 3, nt = (bid >> 2) & 7, mt = (bid >> 5) & 1, gg = bid >> 6;
            GemmP g;
            g.W = (gg ? P.wr1 : P.wu1) + (size_t)ks * 512 * HID;
            g.Asrc = (ks < 2) ? h0n : h1c;
            g.lazyPart = nullptr; g.lazyAdd = nullptr; g.lazyAddStride = 0;
            g.koff = (ks & 1) * 512; g.nchunks = 32;
            g.out = g_pC + (size_t)ks * 128 * 2048 + gg * 1024;
            g.outW = 2048; g.m0 = mt * 64; g.n0 = nt * 128;
            rec_tile(g, smemf);
        }
        grid_barrier(sense);

        // Phase D: layer1 candidate over [h0n | rh1(lazy)] -> pD (x8)
        if (bid < 128) {
            int ks = bid & 7, nt = (bid >> 3) & 7, mt = (bid >> 6) & 1;
            GemmP g;
            g.W = P.wc1 + (size_t)ks * 256 * HID;
            if (ks < 4) {
                g.Asrc = h0n; g.lazyPart = nullptr; g.lazyAdd = nullptr; g.lazyAddStride = 0;
                g.koff = ks * 256;
            } else {
                g.Asrc = h1c; g.lazyPart = g_pC + 1024; g.lazyAdd = P.br1; g.lazyAddStride = 0;
                g.koff = (ks - 4) * 256;
            }
            g.nchunks = 16;
            g.out = g_pD + (size_t)ks * 128 * 1024;
            g.outW = 1024; g.m0 = mt * 64; g.n0 = nt * 128;
            rec_tile(g, smemf);
        }
        grid_barrier(sense);

        // ACT D
        {
            float* seq = g_h1seq + (size_t)t * BH;
            for (int i = bid * 256 + tid; i < BH / 2; i += NBLK * 256) {
                int m = (i * 2) >> 10, n = (i * 2) & 1023;
                float2 su = make_float2(P.bu1[n], P.bu1[n + 1]);
                #pragma unroll
                for (int p = 0; p < 4; ++p) {
                    float2 v = __ldcg((const float2*)&g_pC[((size_t)p * 128 + m) * 2048 + n]);
                    su.x += v.x; su.y += v.y;
                }
                float2 sc = make_float2(P.bc1[n], P.bc1[n + 1]);
                #pragma unroll
                for (int p = 0; p < 8; ++p) {
                    float2 v = __ldcg((const float2*)&g_pD[((size_t)p * 128 + m) * 1024 + n]);
                    sc.x += v.x; sc.y += v.y;
                }
                float2 h = __ldcg((const float2*)&h1c[m * HID + n]);
                float ux = sigf(su.x), uy = sigf(su.y);
                float cx = tanhf(sc.x), cy = tanhf(sc.y);
                float2 o = make_float2(ux * h.x + (1.f - ux) * cx,
                                       uy * h.y + (1.f - uy) * cy);
                *(float2*)&h1n[m * HID + n] = o;
                *(float2*)&seq[m * HID + n] = o;
            }
        }
        grid_barrier(sense);
    }
}

// ---------------- host orchestration ----------------
extern "C" void kernel_launch(void* const* d_in, const int* in_sizes, int n_in,
                              void* d_out, int out_size)
{
    const int*   tok  = (const int*)  d_in[0];
    const float* ihs  = (const float*)d_in[1];
    const float* emb  = (const float*)d_in[2];
    const float* Wout = (const float*)d_in[3];
    const float* bout = (const float*)d_in[4];
    const float* wu0  = (const float*)d_in[5];
    const float* bu0  = (const float*)d_in[6];
    const float* wr0  = (const float*)d_in[7];
    const float* br0  = (const float*)d_in[8];
    const float* wc0  = (const float*)d_in[9];
    const float* bc0  = (const float*)d_in[10];
    const float* wu1  = (const float*)d_in[11];
    const float* bu1  = (const float*)d_in[12];
    const float* wr1  = (const float*)d_in[13];
    const float* br1  = (const float*)d_in[14];
    const float* wc1  = (const float*)d_in[15];
    const float* bc1  = (const float*)d_in[16];

    float *p_x, *p_xu0, *p_xr0, *p_xc0, *p_seq;
    __nv_bfloat16 *p_ah, *p_al, *p_bth, *p_btl;
    cudaGetSymbolAddress((void**)&p_x,   g_x);
    cudaGetSymbolAddress((void**)&p_xu0, g_xu0);
    cudaGetSymbolAddress((void**)&p_xr0, g_xr0);
    cudaGetSymbolAddress((void**)&p_xc0, g_xc0);
    cudaGetSymbolAddress((void**)&p_seq, g_h1seq);
    cudaGetSymbolAddress((void**)&p_ah,  g_ah);
    cudaGetSymbolAddress((void**)&p_al,  g_al);
    cudaGetSymbolAddress((void**)&p_bth, g_bth);
    cudaGetSymbolAddress((void**)&p_btl, g_btl);

    const int MM_SMEM = 2 * MM_STG * 2;   // 2 stages x 4 matrices x 10240 B = 81920
    cudaFuncSetAttribute(mma_gemm<0>, cudaFuncAttributeMaxDynamicSharedMemorySize, MM_SMEM);
    cudaFuncSetAttribute(mma_gemm<1>, cudaFuncAttributeMaxDynamicSharedMemorySize, MM_SMEM);

    // 1) gather embeddings
    gather_kernel<<<TSEQ * BATCH, 256>>>(tok, emb);

    // 2) precompute layer-0 x-projections via tensor cores (mma.sync)
    int n4 = TSEQ * BH / 4;
    cvt_split<<<(n4 + 255) / 256, 256>>>(p_x, p_ah, p_al, n4);
    dim3 tb(32, 8);
    dim3 gpre(64, 8);
    tconv<<<dim3(32, 32), tb>>>(wu0, HID, HID, p_bth, p_btl);
    mma_gemm<0><<<gpre, 256, MM_SMEM>>>(p_ah, p_al, p_bth, p_btl, bu0, p_xu0, HID);
    tconv<<<dim3(32, 32), tb>>>(wr0, HID, HID, p_bth, p_btl);
    mma_gemm<0><<<gpre, 256, MM_SMEM>>>(p_ah, p_al, p_bth, p_btl, br0, p_xr0, HID);
    tconv<<<dim3(32, 32), tb>>>(wc0, HID, HID, p_bth, p_btl);
    mma_gemm<0><<<gpre, 256, MM_SMEM>>>(p_ah, p_al, p_bth, p_btl, bc0, p_xc0, HID);

    // 3) initial hidden state
    init_h<<<(BH + 255) / 256, 256>>>(ihs);

    // 4) persistent recurrence
    RecParams P;
    P.wu0h = wu0 + (size_t)EMB * HID;
    P.wr0h = wr0 + (size_t)EMB * HID;
    P.wc0h = wc0 + (size_t)EMB * HID;
    P.wu1 = wu1; P.wr1 = wr1; P.wc1 = wc1;
    P.bu1 = bu1; P.br1 = br1; P.bc1 = bc1;
    recurrence_kernel<<<NBLK, 256>>>(P);

    // 5) output projection via tensor cores
    cvt_split<<<(n4 + 255) / 256, 256>>>(p_seq, p_ah, p_al, n4);
    tconv<<<dim3(NPAD / 32, 32), tb>>>(Wout, VOCAB, VOCAB, p_bth, p_btl);
    mma_gemm<1><<<dim3(64, NPAD / 128), 256, MM_SMEM>>>(p_ah, p_al, p_bth, p_btl,
                                                         bout, (float*)d_out, VOCAB);

    // 6) final states
    state_out<<<(BH + 255) / 256, 256>>>((float*)d_out, (long long)out_size);
}

// round 6
// speedup vs baseline: 3.7592x; 1.7747x over previous
#include <cuda_runtime.h>
#include <cuda_bf16.h>
#include <math.h>

#define BATCH 128
#define TSEQ  64
#define VOCAB 10000
#define EMB   1024
#define HID   1024
#define NBLK  148
#define BH    (BATCH*HID)
#define NPAD  10240

typedef unsigned long long ull;
typedef __nv_bfloat16 bf16;

__device__ __forceinline__ float sigf(float x) { return 1.f / (1.f + expf(-x)); }

// ---------------- mma.sync helpers ----------------
__device__ __forceinline__ unsigned smem_u32(const void* p) {
    unsigned a;
    asm("{ .reg .u64 t; cvta.to.shared.u64 t, %1; cvt.u32.u64 %0, t; }" : "=r"(a) : "l"(p));
    return a;
}
__device__ __forceinline__ void ldsm4(unsigned* r, unsigned a) {
    asm volatile("ldmatrix.sync.aligned.m8n8.x4.shared.b16 {%0,%1,%2,%3}, [%4];"
                 : "=r"(r[0]), "=r"(r[1]), "=r"(r[2]), "=r"(r[3]) : "r"(a));
}
__device__ __forceinline__ void mma16816(float* c, const unsigned* a, unsigned b0, unsigned b1) {
    asm volatile("mma.sync.aligned.m16n8k16.row.col.f32.bf16.bf16.f32 "
                 "{%0,%1,%2,%3}, {%4,%5,%6,%7}, {%8,%9}, {%0,%1,%2,%3};"
                 : "+f"(c[0]), "+f"(c[1]), "+f"(c[2]), "+f"(c[3])
                 : "r"(a[0]), "r"(a[1]), "r"(a[2]), "r"(a[3]), "r"(b0), "r"(b1));
}
__device__ __forceinline__ void cpa16(unsigned saddr, const void* g) {     // L1-cached
    asm volatile("cp.async.ca.shared.global [%0], [%1], 16;" :: "r"(saddr), "l"(g));
}
__device__ __forceinline__ void cpg16(unsigned saddr, const void* g) {     // L2-only
    asm volatile("cp.async.cg.shared.global [%0], [%1], 16;" :: "r"(saddr), "l"(g));
}

// ---------------- device scratch ----------------
__device__ float g_x[TSEQ*BH];
__device__ float g_xu0[TSEQ*BH];
__device__ float g_xr0[TSEQ*BH];
__device__ float g_xc0[TSEQ*BH];
__device__ float g_h0buf[2*BH];
__device__ float g_h1buf[2*BH];
__device__ float g_h1seq[TSEQ*BH];
__device__ float g_pA[8*128*2048];
__device__ float g_pB[16*128*1024];
__device__ float g_pC[8*128*2048];
__device__ float g_pD[16*128*1024];
__device__ bf16 g_ah[TSEQ*BH];
__device__ bf16 g_al[TSEQ*BH];
__device__ bf16 g_bth[NPAD*1024];
__device__ bf16 g_btl[NPAD*1024];
// recurrence weight transposes [gate][N][K]
__device__ bf16 g_wt0h[3*1024*1024];
__device__ bf16 g_wt0l[3*1024*1024];
__device__ bf16 g_wt1h[3*1024*2048];
__device__ bf16 g_wt1l[3*1024*2048];
// hidden-state hi/lo splits
__device__ bf16 g_h0h[2*BH], g_h0l[2*BH];
__device__ bf16 g_h1h[2*BH], g_h1l[2*BH];
__device__ bf16 g_rh0h[BH], g_rh0l[BH];
__device__ bf16 g_rh1h[BH], g_rh1l[BH];
__device__ unsigned g_barcnt;
__device__ volatile unsigned g_barsense;

__device__ __forceinline__ void bsplit2(bf16* bh, bf16* bl, size_t idx, float2 v) {
    bf16 h0 = __float2bfloat16(v.x), h1 = __float2bfloat16(v.y);
    bf16 l0 = __float2bfloat16(v.x - __bfloat162float(h0));
    bf16 l1 = __float2bfloat16(v.y - __bfloat162float(h1));
    *(__nv_bfloat162*)(bh + idx) = __halves2bfloat162(h0, h1);
    *(__nv_bfloat162*)(bl + idx) = __halves2bfloat162(l0, l1);
}

// ---------------- small kernels ----------------
__global__ void gather_kernel(const int* __restrict__ tok, const float* __restrict__ emb) {
    int row = blockIdx.x;
    int t = row >> 7, b = row & 127;
    int token = tok[b * TSEQ + t];
    const float4* src = (const float4*)(emb + (size_t)token * EMB);
    float4* dst = (float4*)(g_x + (size_t)row * EMB);
    dst[threadIdx.x] = src[threadIdx.x];
}

__global__ void init_h(const float* __restrict__ ihs) {
    int i = (blockIdx.x * blockDim.x + threadIdx.x) * 2;
    if (i < BH) {
        float2 a = *(const float2*)&ihs[i];
        float2 b = *(const float2*)&ihs[BH + i];
        *(float2*)&g_h0buf[i] = a;
        *(float2*)&g_h1buf[i] = b;
        bsplit2(g_h0h, g_h0l, i, a);
        bsplit2(g_h1h, g_h1l, i, b);
    }
}

__global__ void state_out(float* __restrict__ out, long long out_size) {
    long long i = (long long)blockIdx.x * blockDim.x + threadIdx.x;
    long long base = (long long)BATCH * TSEQ * VOCAB;
    if (i < BH) {
        if (base + i < out_size)      out[base + i]      = g_h0buf[i];
        if (base + BH + i < out_size) out[base + BH + i] = g_h1buf[i];
    }
}

__global__ void cvt_split(const float* __restrict__ src, bf16* __restrict__ oh,
                          bf16* __restrict__ ol, int n4) {
    int i = blockIdx.x * blockDim.x + threadIdx.x;
    if (i >= n4) return;
    float4 v = ((const float4*)src)[i];
    bsplit2(oh, ol, (size_t)i * 4,     make_float2(v.x, v.y));
    bsplit2(oh, ol, (size_t)i * 4 + 2, make_float2(v.z, v.w));
}

// transpose + split: W[k][n] (ldw) -> th/tl [n][k] with row stride ldo; zero-pad n>=N
__global__ void tconv(const float* __restrict__ W, int ldw, int N, int ldo,
                      bf16* __restrict__ th, bf16* __restrict__ tl) {
    __shared__ float t[32][33];
    int n0 = blockIdx.x * 32, k0 = blockIdx.y * 32;
    int tx = threadIdx.x, ty = threadIdx.y;
    #pragma unroll
    for (int r = 0; r < 4; ++r) {
        int k = k0 + ty + r * 8, n = n0 + tx;
        t[ty + r * 8][tx] = (n < N) ? W[(size_t)k * ldw + n] : 0.f;
    }
    __syncthreads();
    #pragma unroll
    for (int r = 0; r < 4; ++r) {
        int n = n0 + ty + r * 8, k = k0 + tx;
        float x = t[tx][ty + r * 8];
        bf16 hh = __float2bfloat16(x);
        th[(size_t)n * ldo + k] = hh;
        tl[(size_t)n * ldo + k] = __float2bfloat16(x - __bfloat162float(hh));
    }
}

// ---------------- mma.sync bf16-split GEMM (standalone; pre + logits) ----------------
#define MM_LD 40
#define MM_MS (128*MM_LD)
#define MM_STG (4*MM_MS)

template<int MODE>
__global__ __launch_bounds__(256, 1)
void mma_gemm(const bf16* __restrict__ Ah, const bf16* __restrict__ Al,
              const bf16* __restrict__ Bh, const bf16* __restrict__ Bl,
              const float* __restrict__ bias, float* __restrict__ C, int N)
{
    extern __shared__ __align__(16) bf16 sm[];
    const int tid = threadIdx.x, w = tid >> 5, l = tid & 31;
    const int m0 = blockIdx.x * 128, n0 = blockIdx.y * 128;
    const int mw = (w >> 2) * 64, nw = (w & 3) * 32;
    const unsigned sbase = smem_u32(sm);

    float acc[4][4][4];
    #pragma unroll
    for (int i = 0; i < 4; ++i)
        #pragma unroll
        for (int j = 0; j < 4; ++j)
            #pragma unroll
            for (int q = 0; q < 4; ++q) acc[i][j][q] = 0.f;

    auto stage_load = [&](int c, int s) {
        int kc = c * 32;
        unsigned sb = sbase + (unsigned)(s * MM_STG) * 2;
        #pragma unroll
        for (int l2 = 0; l2 < 2; ++l2) {
            int u = tid + l2 * 256;
            int row = u >> 2, q = u & 3;
            unsigned soff = (unsigned)(row * MM_LD + q * 8) * 2;
            size_t ga = (size_t)(m0 + row) * 1024 + kc + q * 8;
            size_t gb = (size_t)(n0 + row) * 1024 + kc + q * 8;
            cpa16(sb + 0 * MM_MS * 2 + soff, Ah + ga);
            cpa16(sb + 1 * MM_MS * 2 + soff, Al + ga);
            cpa16(sb + 2 * MM_MS * 2 + soff, Bh + gb);
            cpa16(sb + 3 * MM_MS * 2 + soff, Bl + gb);
        }
    };

    stage_load(0, 0);
    asm volatile("cp.async.commit_group;" ::: "memory");
    const int ldrow = ((l >> 3) & 1) * 8 + (l & 7);
    const int ldcol = (l >> 4) * 8;

    for (int c = 0; c < 32; ++c) {
        if (c + 1 < 32) {
            stage_load(c + 1, (c + 1) & 1);
            asm volatile("cp.async.commit_group;" ::: "memory");
            asm volatile("cp.async.wait_group 1;" ::: "memory");
        } else {
            asm volatile("cp.async.wait_group 0;" ::: "memory");
        }
        __syncthreads();
        unsigned sb = sbase + (unsigned)((c & 1) * MM_STG) * 2;
        #pragma unroll
        for (int kk = 0; kk < 2; ++kk) {
            unsigned aH[4][4], aL[4][4], bH[4][2], bL[4][2];
            #pragma unroll
            for (int mt = 0; mt < 4; ++mt) {
                int r = mw + mt * 16 + ldrow;
                unsigned ad = sb + (unsigned)(r * MM_LD + kk * 16 + ldcol) * 2;
                ldsm4(aH[mt], ad);
                ldsm4(aL[mt], ad + MM_MS * 2);
            }
            #pragma unroll
            for (int p = 0; p < 2; ++p) {
                int r = nw + p * 16 + ldrow;
                unsigned bd = sb + (unsigned)(2 * MM_MS + r * MM_LD + kk * 16 + ldcol) * 2;
                unsigned t0[4], t1[4];
                ldsm4(t0, bd);
                ldsm4(t1, bd + MM_MS * 2);
                bH[2*p][0] = t0[0]; bH[2*p][1] = t0[2];
                bH[2*p+1][0] = t0[1]; bH[2*p+1][1] = t0[3];
                bL[2*p][0] = t1[0]; bL[2*p][1] = t1[2];
                bL[2*p+1][0] = t1[1]; bL[2*p+1][1] = t1[3];
            }
            #pragma unroll
            for (int mt = 0; mt < 4; ++mt)
                #pragma unroll
                for (int nt = 0; nt < 4; ++nt) {
                    mma16816(acc[mt][nt], aH[mt], bH[nt][0], bH[nt][1]);
                    mma16816(acc[mt][nt], aH[mt], bL[nt][0], bL[nt][1]);
                    mma16816(acc[mt][nt], aL[mt], bH[nt][0], bH[nt][1]);
                }
        }
        __syncthreads();
    }

    int g = l >> 2, tg = l & 3;
    #pragma unroll
    for (int mt = 0; mt < 4; ++mt) {
        int r0 = m0 + mw + mt * 16 + g;
        int r1 = r0 + 8;
        float *crow0, *crow1;
        if (MODE == 0) {
            crow0 = C + (size_t)r0 * N;
            crow1 = C + (size_t)r1 * N;
        } else {
            crow0 = C + ((size_t)(r0 & 127) * TSEQ + (r0 >> 7)) * N;
            crow1 = C + ((size_t)(r1 & 127) * TSEQ + (r1 >> 7)) * N;
        }
        #pragma unroll
        for (int nt = 0; nt < 4; ++nt) {
            int n = n0 + nw + nt * 8 + tg * 2;
            if (MODE == 0 || n < N) {
                float2 bv = *(const float2*)&bias[n];
                *(float2*)&crow0[n] = make_float2(acc[mt][nt][0] + bv.x, acc[mt][nt][1] + bv.y);
                *(float2*)&crow1[n] = make_float2(acc[mt][nt][2] + bv.x, acc[mt][nt][3] + bv.y);
            }
        }
    }
}

// ---------------- recurrence MMA tile (device fn; partial output, no bias) ----------------
__device__ __noinline__ void rec_mma(
    const bf16* Ah, const bf16* Al, int akoff,
    const bf16* Bh, const bf16* Bl, int bkoff, int ldb,
    int n0, int kchunks, float* outp, int outW, bf16* sm)
{
    const int tid = threadIdx.x, w = tid >> 5, l = tid & 31;
    const int mw = (w >> 2) * 64, nw = (w & 3) * 32;
    const unsigned sbase = smem_u32(sm);

    float acc[4][4][4];
    #pragma unroll
    for (int i = 0; i < 4; ++i)
        #pragma unroll
        for (int j = 0; j < 4; ++j)
            #pragma unroll
            for (int q = 0; q < 4; ++q) acc[i][j][q] = 0.f;

    auto stage_load = [&](int c, int s) {
        int kc = c * 32;
        unsigned sb = sbase + (unsigned)(s * MM_STG) * 2;
        #pragma unroll
        for (int l2 = 0; l2 < 2; ++l2) {
            int u = tid + l2 * 256;
            int row = u >> 2, q = u & 3;
            unsigned soff = (unsigned)(row * MM_LD + q * 8) * 2;
            size_t ga = (size_t)row * 1024 + akoff + kc + q * 8;
            size_t gb = (size_t)(n0 + row) * ldb + bkoff + kc + q * 8;
            cpg16(sb + 0 * MM_MS * 2 + soff, Ah + ga);     // .cg: h data recurs in-launch
            cpg16(sb + 1 * MM_MS * 2 + soff, Al + ga);
            cpg16(sb + 2 * MM_MS * 2 + soff, Bh + gb);
            cpg16(sb + 3 * MM_MS * 2 + soff, Bl + gb);
        }
    };

    stage_load(0, 0);
    asm volatile("cp.async.commit_group;" ::: "memory");
    const int ldrow = ((l >> 3) & 1) * 8 + (l & 7);
    const int ldcol = (l >> 4) * 8;

    for (int c = 0; c < kchunks; ++c) {
        if (c + 1 < kchunks) {
            stage_load(c + 1, (c + 1) & 1);
            asm volatile("cp.async.commit_group;" ::: "memory");
            asm volatile("cp.async.wait_group 1;" ::: "memory");
        } else {
            asm volatile("cp.async.wait_group 0;" ::: "memory");
        }
        __syncthreads();
        unsigned sb = sbase + (unsigned)((c & 1) * MM_STG) * 2;
        #pragma unroll
        for (int kk = 0; kk < 2; ++kk) {
            unsigned aH[4][4], aL[4][4], bH[4][2], bL[4][2];
            #pragma unroll
            for (int mt = 0; mt < 4; ++mt) {
                int r = mw + mt * 16 + ldrow;
                unsigned ad = sb + (unsigned)(r * MM_LD + kk * 16 + ldcol) * 2;
                ldsm4(aH[mt], ad);
                ldsm4(aL[mt], ad + MM_MS * 2);
            }
            #pragma unroll
            for (int p = 0; p < 2; ++p) {
                int r = nw + p * 16 + ldrow;
                unsigned bd = sb + (unsigned)(2 * MM_MS + r * MM_LD + kk * 16 + ldcol) * 2;
                unsigned t0[4], t1[4];
                ldsm4(t0, bd);
                ldsm4(t1, bd + MM_MS * 2);
                bH[2*p][0] = t0[0]; bH[2*p][1] = t0[2];
                bH[2*p+1][0] = t0[1]; bH[2*p+1][1] = t0[3];
                bL[2*p][0] = t1[0]; bL[2*p][1] = t1[2];
                bL[2*p+1][0] = t1[1]; bL[2*p+1][1] = t1[3];
            }
            #pragma unroll
            for (int mt = 0; mt < 4; ++mt)
                #pragma unroll
                for (int nt = 0; nt < 4; ++nt) {
                    mma16816(acc[mt][nt], aH[mt], bH[nt][0], bH[nt][1]);
                    mma16816(acc[mt][nt], aH[mt], bL[nt][0], bL[nt][1]);
                    mma16816(acc[mt][nt], aL[mt], bH[nt][0], bH[nt][1]);
                }
        }
        __syncthreads();
    }

    int g = l >> 2, tg = l & 3;
    #pragma unroll
    for (int mt = 0; mt < 4; ++mt) {
        int r0 = mw + mt * 16 + g;
        int r1 = r0 + 8;
        #pragma unroll
        for (int nt = 0; nt < 4; ++nt) {
            int n = n0 + nw + nt * 8 + tg * 2;
            *(float2*)&outp[(size_t)r0 * outW + n] = make_float2(acc[mt][nt][0], acc[mt][nt][1]);
            *(float2*)&outp[(size_t)r1 * outW + n] = make_float2(acc[mt][nt][2], acc[mt][nt][3]);
        }
    }
}

// ---------------- persistent recurrence ----------------
struct RecParams {
    const float *bu1, *br1, *bc1;
};

__device__ __forceinline__ void grid_barrier(unsigned& sense) {
    __syncthreads();
    if (threadIdx.x == 0) {
        unsigned next = sense ^ 1u;
        __threadfence();
        if (atomicAdd(&g_barcnt, 1u) == NBLK - 1) {
            g_barcnt = 0;
            __threadfence();
            g_barsense = next;
        } else {
            while (g_barsense != next) __nanosleep(32);
        }
    }
    sense ^= 1u;
    __syncthreads();
}

__global__ __launch_bounds__(256, 1)
void recurrence_kernel(RecParams P)
{
    extern __shared__ __align__(16) bf16 sm[];
    unsigned sense = 0;
    const int bid = blockIdx.x;
    const int tid = threadIdx.x;

    for (int t = 0; t < TSEQ; ++t) {
        const int cur = t & 1, nxt = cur ^ 1;
        const float* xu = g_xu0 + (size_t)t * BH;
        const float* xr = g_xr0 + (size_t)t * BH;
        const float* xc = g_xc0 + (size_t)t * BH;
        float* h0c = g_h0buf + (size_t)cur * BH;
        float* h0n = g_h0buf + (size_t)nxt * BH;
        float* h1c = g_h1buf + (size_t)cur * BH;
        float* h1n = g_h1buf + (size_t)nxt * BH;
        bf16 *h0ch = g_h0h + (size_t)cur * BH, *h0cl = g_h0l + (size_t)cur * BH;
        bf16 *h0nh = g_h0h + (size_t)nxt * BH, *h0nl = g_h0l + (size_t)nxt * BH;
        bf16 *h1ch = g_h1h + (size_t)cur * BH, *h1cl = g_h1l + (size_t)cur * BH;
        bf16 *h1nh = g_h1h + (size_t)nxt * BH, *h1nl = g_h1l + (size_t)nxt * BH;

        // Phase A: layer0 u,r h-part -> pA  (2 gates x 8 N x 8 K = 128 CTAs)
        if (bid < 128) {
            int gg = bid >> 6, ks = bid & 7, nt = (bid >> 3) & 7;
            rec_mma(h0ch, h0cl, ks * 128,
                    g_wt0h + (size_t)gg * 1024 * 1024, g_wt0l + (size_t)gg * 1024 * 1024,
                    ks * 128, 1024, nt * 128, 4,
                    g_pA + (size_t)ks * 128 * 2048 + gg * 1024, 2048, sm);
        }
        grid_barrier(sense);

        // ACT A: rh0 = sig(xr + sum pA[r]) * h0c -> hi/lo
        for (int i = bid * 256 + tid; i < BH / 2; i += NBLK * 256) {
            size_t idx = (size_t)i * 2;
            int m = (int)(idx >> 10), n = (int)(idx & 1023);
            float2 s = *(const float2*)&xr[idx];
            #pragma unroll
            for (int p = 0; p < 8; ++p) {
                float2 v = __ldcg((const float2*)&g_pA[((size_t)p * 128 + m) * 2048 + 1024 + n]);
                s.x += v.x; s.y += v.y;
            }
            float2 h = __ldcg((const float2*)&h0c[idx]);
            bsplit2(g_rh0h, g_rh0l, idx, make_float2(sigf(s.x) * h.x, sigf(s.y) * h.y));
        }
        grid_barrier(sense);

        // Phase B: layer0 candidate -> pB  (8 N x 16 K = 128 CTAs)
        if (bid < 128) {
            int ks = bid & 15, nt = bid >> 4;
            rec_mma(g_rh0h, g_rh0l, ks * 64,
                    g_wt0h + (size_t)2 * 1024 * 1024, g_wt0l + (size_t)2 * 1024 * 1024,
                    ks * 64, 1024, nt * 128, 2,
                    g_pB + (size_t)ks * 128 * 1024, 1024, sm);
        }
        grid_barrier(sense);

        // ACT B: h0n = u*h0c + (1-u)*tanh(xc + sum pB); write fp32 + hi/lo
        for (int i = bid * 256 + tid; i < BH / 2; i += NBLK * 256) {
            size_t idx = (size_t)i * 2;
            int m = (int)(idx >> 10), n = (int)(idx & 1023);
            float2 su = *(const float2*)&xu[idx];
            #pragma unroll
            for (int p = 0; p < 8; ++p) {
                float2 v = __ldcg((const float2*)&g_pA[((size_t)p * 128 + m) * 2048 + n]);
                su.x += v.x; su.y += v.y;
            }
            float2 sc = *(const float2*)&xc[idx];
            #pragma unroll
            for (int p = 0; p < 16; ++p) {
                float2 v = __ldcg((const float2*)&g_pB[((size_t)p * 128 + m) * 1024 + n]);
                sc.x += v.x; sc.y += v.y;
            }
            float2 h = __ldcg((const float2*)&h0c[idx]);
            float ux = sigf(su.x), uy = sigf(su.y);
            float2 o = make_float2(ux * h.x + (1.f - ux) * tanhf(sc.x),
                                   uy * h.y + (1.f - uy) * tanhf(sc.y));
            *(float2*)&h0n[idx] = o;
            bsplit2(h0nh, h0nl, idx, o);
        }
        grid_barrier(sense);

        // Phase C: layer1 u,r over [h0n | h1c], K=2048 -> pC (2 x 8 N x 8 K = 128)
        if (bid < 128) {
            int gg = bid >> 6, ks = bid & 7, nt = (bid >> 3) & 7;
            int koff = ks * 256;
            const bf16* ah = (koff < 1024) ? h0nh : h1ch;
            const bf16* al = (koff < 1024) ? h0nl : h1cl;
            rec_mma(ah, al, koff & 1023,
                    g_wt1h + (size_t)gg * 1024 * 2048, g_wt1l + (size_t)gg * 1024 * 2048,
                    koff, 2048, nt * 128, 8,
                    g_pC + (size_t)ks * 128 * 2048 + gg * 1024, 2048, sm);
        }
        grid_barrier(sense);

        // ACT C: rh1 = sig(br1 + sum pC[r]) * h1c -> hi/lo
        for (int i = bid * 256 + tid; i < BH / 2; i += NBLK * 256) {
            size_t idx = (size_t)i * 2;
            int m = (int)(idx >> 10), n = (int)(idx & 1023);
            float2 s = *(const float2*)&P.br1[n];
            #pragma unroll
            for (int p = 0; p < 8; ++p) {
                float2 v = __ldcg((const float2*)&g_pC[((size_t)p * 128 + m) * 2048 + 1024 + n]);
                s.x += v.x; s.y += v.y;
            }
            float2 h = __ldcg((const float2*)&h1c[idx]);
            bsplit2(g_rh1h, g_rh1l, idx, make_float2(sigf(s.x) * h.x, sigf(s.y) * h.y));
        }
        grid_barrier(sense);

        // Phase D: layer1 candidate over [h0n | rh1], K=2048 -> pD (8 N x 16 K = 128)
        if (bid < 128) {
            int ks = bid & 15, nt = bid >> 4;
            int koff = ks * 128;
            const bf16* ah = (koff < 1024) ? h0nh : g_rh1h;
            const bf16* al = (koff < 1024) ? h0nl : g_rh1l;
            rec_mma(ah, al, koff & 1023,
                    g_wt1h + (size_t)2 * 1024 * 2048, g_wt1l + (size_t)2 * 1024 * 2048,
                    koff, 2048, nt * 128, 4,
                    g_pD + (size_t)ks * 128 * 1024, 1024, sm);
        }
        grid_barrier(sense);

        // ACT D: h1n = u1*h1c + (1-u1)*tanh(bc1 + sum pD); fp32 + hi/lo + seq
        {
            float* seq = g_h1seq + (size_t)t * BH;
            for (int i = bid * 256 + tid; i < BH / 2; i += NBLK * 256) {
                size_t idx = (size_t)i * 2;
                int m = (int)(idx >> 10), n = (int)(idx & 1023);
                float2 su = *(const float2*)&P.bu1[n];
                #pragma unroll
                for (int p = 0; p < 8; ++p) {
                    float2 v = __ldcg((const float2*)&g_pC[((size_t)p * 128 + m) * 2048 + n]);
                    su.x += v.x; su.y += v.y;
                }
                float2 sc = *(const float2*)&P.bc1[n];
                #pragma unroll
                for (int p = 0; p < 16; ++p) {
                    float2 v = __ldcg((const float2*)&g_pD[((size_t)p * 128 + m) * 1024 + n]);
                    sc.x += v.x; sc.y += v.y;
                }
                float2 h = __ldcg((const float2*)&h1c[idx]);
                float ux = sigf(su.x), uy = sigf(su.y);
                float2 o = make_float2(ux * h.x + (1.f - ux) * tanhf(sc.x),
                                       uy * h.y + (1.f - uy) * tanhf(sc.y));
                *(float2*)&h1n[idx] = o;
                *(float2*)&seq[idx] = o;
                bsplit2(h1nh, h1nl, idx, o);
            }
        }
        grid_barrier(sense);
    }
}

// ---------------- host orchestration ----------------
extern "C" void kernel_launch(void* const* d_in, const int* in_sizes, int n_in,
                              void* d_out, int out_size)
{
    const int*   tok  = (const int*)  d_in[0];
    const float* ihs  = (const float*)d_in[1];
    const float* emb  = (const float*)d_in[2];
    const float* Wout = (const float*)d_in[3];
    const float* bout = (const float*)d_in[4];
    const float* wu0  = (const float*)d_in[5];
    const float* bu0  = (const float*)d_in[6];
    const float* wr0  = (const float*)d_in[7];
    const float* br0  = (const float*)d_in[8];
    const float* wc0  = (const float*)d_in[9];
    const float* bc0  = (const float*)d_in[10];
    const float* wu1  = (const float*)d_in[11];
    const float* bu1  = (const float*)d_in[12];
    const float* wr1  = (const float*)d_in[13];
    const float* br1  = (const float*)d_in[14];
    const float* wc1  = (const float*)d_in[15];
    const float* bc1  = (const float*)d_in[16];

    float *p_x, *p_xu0, *p_xr0, *p_xc0, *p_seq;
    bf16 *p_ah, *p_al, *p_bth, *p_btl, *p_wt0h, *p_wt0l, *p_wt1h, *p_wt1l;
    cudaGetSymbolAddress((void**)&p_x,   g_x);
    cudaGetSymbolAddress((void**)&p_xu0, g_xu0);
    cudaGetSymbolAddress((void**)&p_xr0, g_xr0);
    cudaGetSymbolAddress((void**)&p_xc0, g_xc0);
    cudaGetSymbolAddress((void**)&p_seq, g_h1seq);
    cudaGetSymbolAddress((void**)&p_ah,  g_ah);
    cudaGetSymbolAddress((void**)&p_al,  g_al);
    cudaGetSymbolAddress((void**)&p_bth, g_bth);
    cudaGetSymbolAddress((void**)&p_btl, g_btl);
    cudaGetSymbolAddress((void**)&p_wt0h, g_wt0h);
    cudaGetSymbolAddress((void**)&p_wt0l, g_wt0l);
    cudaGetSymbolAddress((void**)&p_wt1h, g_wt1h);
    cudaGetSymbolAddress((void**)&p_wt1l, g_wt1l);

    const int MM_SMEM = 2 * MM_STG * 2;   // 81920 B
    cudaFuncSetAttribute(mma_gemm<0>, cudaFuncAttributeMaxDynamicSharedMemorySize, MM_SMEM);
    cudaFuncSetAttribute(mma_gemm<1>, cudaFuncAttributeMaxDynamicSharedMemorySize, MM_SMEM);
    cudaFuncSetAttribute(recurrence_kernel, cudaFuncAttributeMaxDynamicSharedMemorySize, MM_SMEM);

    // 1) gather embeddings
    gather_kernel<<<TSEQ * BATCH, 256>>>(tok, emb);

    // 2) precompute layer-0 x-projections (mma.sync)
    int n4 = TSEQ * BH / 4;
    cvt_split<<<(n4 + 255) / 256, 256>>>(p_x, p_ah, p_al, n4);
    dim3 tb(32, 8);
    dim3 gpre(64, 8);
    tconv<<<dim3(32, 32), tb>>>(wu0, HID, HID, 1024, p_bth, p_btl);
    mma_gemm<0><<<gpre, 256, MM_SMEM>>>(p_ah, p_al, p_bth, p_btl, bu0, p_xu0, HID);
    tconv<<<dim3(32, 32), tb>>>(wr0, HID, HID, 1024, p_bth, p_btl);
    mma_gemm<0><<<gpre, 256, MM_SMEM>>>(p_ah, p_al, p_bth, p_btl, br0, p_xr0, HID);
    tconv<<<dim3(32, 32), tb>>>(wc0, HID, HID, 1024, p_bth, p_btl);
    mma_gemm<0><<<gpre, 256, MM_SMEM>>>(p_ah, p_al, p_bth, p_btl, bc0, p_xc0, HID);

    // 3) recurrence weight transposes (h-part of layer0; full layer1)
    const size_t EH = (size_t)EMB * HID;
    tconv<<<dim3(32, 32), tb>>>(wu0 + EH, HID, HID, 1024, p_wt0h,               p_wt0l);
    tconv<<<dim3(32, 32), tb>>>(wr0 + EH, HID, HID, 1024, p_wt0h + 1024*1024,   p_wt0l + 1024*1024);
    tconv<<<dim3(32, 32), tb>>>(wc0 + EH, HID, HID, 1024, p_wt0h + 2*1024*1024, p_wt0l + 2*1024*1024);
    tconv<<<dim3(32, 64), tb>>>(wu1, HID, HID, 2048, p_wt1h,               p_wt1l);
    tconv<<<dim3(32, 64), tb>>>(wr1, HID, HID, 2048, p_wt1h + 1024*2048,   p_wt1l + 1024*2048);
    tconv<<<dim3(32, 64), tb>>>(wc1, HID, HID, 2048, p_wt1h + 2*1024*2048, p_wt1l + 2*1024*2048);

    // 4) initial hidden state (fp32 + hi/lo)
    init_h<<<(BH / 2 + 255) / 256, 256>>>(ihs);

    // 5) persistent recurrence (tensor-core phases + fused ACT)
    RecParams P{bu1, br1, bc1};
    recurrence_kernel<<<NBLK, 256, MM_SMEM>>>(P);

    // 6) output projection
    cvt_split<<<(n4 + 255) / 256, 256>>>(p_seq, p_ah, p_al, n4);
    tconv<<<dim3(NPAD / 32, 32), tb>>>(Wout, VOCAB, VOCAB, 1024, p_bth, p_btl);
    mma_gemm<1><<<dim3(64, NPAD / 128), 256, MM_SMEM>>>(p_ah, p_al, p_bth, p_btl,
                                                         bout, (float*)d_out, VOCAB);

    // 7) final states
    state_out<<<(BH + 255) / 256, 256>>>((float*)d_out, (long long)out_size);
}

// round 7
// speedup vs baseline: 3.8809x; 1.0324x over previous
#include <cuda_runtime.h>
#include <cuda_bf16.h>
#include <math.h>

#define BATCH 128
#define TSEQ  64
#define VOCAB 10000
#define EMB   1024
#define HID   1024
#define NBLK  148
#define BH    (BATCH*HID)
#define NPAD  10240
#define XP3   3072

typedef unsigned long long ull;
typedef __nv_bfloat16 bf16;

__device__ __forceinline__ float sigf(float x) { return 1.f / (1.f + expf(-x)); }

// ---------------- mma.sync helpers ----------------
__device__ __forceinline__ unsigned smem_u32(const void* p) {
    unsigned a;
    asm("{ .reg .u64 t; cvta.to.shared.u64 t, %1; cvt.u32.u64 %0, t; }" : "=r"(a) : "l"(p));
    return a;
}
__device__ __forceinline__ void ldsm4(unsigned* r, unsigned a) {
    asm volatile("ldmatrix.sync.aligned.m8n8.x4.shared.b16 {%0,%1,%2,%3}, [%4];"
                 : "=r"(r[0]), "=r"(r[1]), "=r"(r[2]), "=r"(r[3]) : "r"(a));
}
__device__ __forceinline__ void mma16816(float* c, const unsigned* a, unsigned b0, unsigned b1) {
    asm volatile("mma.sync.aligned.m16n8k16.row.col.f32.bf16.bf16.f32 "
                 "{%0,%1,%2,%3}, {%4,%5,%6,%7}, {%8,%9}, {%0,%1,%2,%3};"
                 : "+f"(c[0]), "+f"(c[1]), "+f"(c[2]), "+f"(c[3])
                 : "r"(a[0]), "r"(a[1]), "r"(a[2]), "r"(a[3]), "r"(b0), "r"(b1));
}
__device__ __forceinline__ void cpa16(unsigned saddr, const void* g) {
    asm volatile("cp.async.ca.shared.global [%0], [%1], 16;" :: "r"(saddr), "l"(g));
}
__device__ __forceinline__ void cpg16(unsigned saddr, const void* g) {
    asm volatile("cp.async.cg.shared.global [%0], [%1], 16;" :: "r"(saddr), "l"(g));
}

// ---------------- device scratch ----------------
__device__ float g_x[TSEQ*BH];
__device__ float g_xp[TSEQ*BATCH*XP3];   // fused x-preacts [t*B+b][u|r|c]
__device__ float g_h0buf[2*BH];
__device__ float g_h1buf[2*BH];
__device__ float g_h1seq[TSEQ*BH];
__device__ float g_pA[8*128*2048];
__device__ float g_pB[16*128*1024];
__device__ float g_pC[8*128*2048];
__device__ float g_pD[16*128*1024];
__device__ float g_bias3[XP3];
__device__ bf16 g_ah[TSEQ*BH];
__device__ bf16 g_al[TSEQ*BH];
__device__ bf16 g_bth[NPAD*1024];
__device__ bf16 g_btl[NPAD*1024];
__device__ bf16 g_wt0h[3*1024*1024];
__device__ bf16 g_wt0l[3*1024*1024];
__device__ bf16 g_wt1h[3*1024*2048];
__device__ bf16 g_wt1l[3*1024*2048];
__device__ bf16 g_h0h[2*BH], g_h0l[2*BH];
__device__ bf16 g_h1h[2*BH], g_h1l[2*BH];
__device__ bf16 g_rh0h[BH], g_rh0l[BH];
__device__ bf16 g_rh1h[BH], g_rh1l[BH];
__device__ unsigned g_barcnt;
__device__ volatile unsigned g_barsense;

__device__ __forceinline__ void bsplit2(bf16* bh, bf16* bl, size_t idx, float2 v) {
    bf16 h0 = __float2bfloat16(v.x), h1 = __float2bfloat16(v.y);
    bf16 l0 = __float2bfloat16(v.x - __bfloat162float(h0));
    bf16 l1 = __float2bfloat16(v.y - __bfloat162float(h1));
    *(__nv_bfloat162*)(bh + idx) = __halves2bfloat162(h0, h1);
    *(__nv_bfloat162*)(bl + idx) = __halves2bfloat162(l0, l1);
}

// ---------------- small kernels ----------------
__global__ void gather_kernel(const int* __restrict__ tok, const float* __restrict__ emb) {
    int row = blockIdx.x;
    int t = row >> 7, b = row & 127;
    int token = tok[b * TSEQ + t];
    const float4* src = (const float4*)(emb + (size_t)token * EMB);
    float4* dst = (float4*)(g_x + (size_t)row * EMB);
    dst[threadIdx.x] = src[threadIdx.x];
}

__global__ void init_h(const float* __restrict__ ihs) {
    int i = (blockIdx.x * blockDim.x + threadIdx.x) * 2;
    if (i < BH) {
        float2 a = *(const float2*)&ihs[i];
        float2 b = *(const float2*)&ihs[BH + i];
        *(float2*)&g_h0buf[i] = a;
        *(float2*)&g_h1buf[i] = b;
        bsplit2(g_h0h, g_h0l, i, a);
        bsplit2(g_h1h, g_h1l, i, b);
    }
}

__global__ void concat_bias(const float* __restrict__ bu, const float* __restrict__ br,
                            const float* __restrict__ bc) {
    int i = blockIdx.x * blockDim.x + threadIdx.x;
    if (i < 1024) {
        g_bias3[i]        = bu[i];
        g_bias3[1024 + i] = br[i];
        g_bias3[2048 + i] = bc[i];
    }
}

__global__ void state_out(float* __restrict__ out, long long out_size) {
    long long i = (long long)blockIdx.x * blockDim.x + threadIdx.x;
    long long base = (long long)BATCH * TSEQ * VOCAB;
    if (i < BH) {
        if (base + i < out_size)      out[base + i]      = g_h0buf[i];
        if (base + BH + i < out_size) out[base + BH + i] = g_h1buf[i];
    }
}

__global__ void cvt_split(const float* __restrict__ src, bf16* __restrict__ oh,
                          bf16* __restrict__ ol, int n4) {
    int i = blockIdx.x * blockDim.x + threadIdx.x;
    if (i >= n4) return;
    float4 v = ((const float4*)src)[i];
    bsplit2(oh, ol, (size_t)i * 4,     make_float2(v.x, v.y));
    bsplit2(oh, ol, (size_t)i * 4 + 2, make_float2(v.z, v.w));
}

// transpose + split: W[k][n] (ldw) -> th/tl [n][k] (ldo); zero-pad n>=N
__global__ void tconv(const float* __restrict__ W, int ldw, int N, int ldo,
                      bf16* __restrict__ th, bf16* __restrict__ tl) {
    __shared__ float t[32][33];
    int n0 = blockIdx.x * 32, k0 = blockIdx.y * 32;
    int tx = threadIdx.x, ty = threadIdx.y;
    #pragma unroll
    for (int r = 0; r < 4; ++r) {
        int k = k0 + ty + r * 8, n = n0 + tx;
        t[ty + r * 8][tx] = (n < N) ? W[(size_t)k * ldw + n] : 0.f;
    }
    __syncthreads();
    #pragma unroll
    for (int r = 0; r < 4; ++r) {
        int n = n0 + ty + r * 8, k = k0 + tx;
        float x = t[tx][ty + r * 8];
        bf16 hh = __float2bfloat16(x);
        th[(size_t)n * ldo + k] = hh;
        tl[(size_t)n * ldo + k] = __float2bfloat16(x - __bfloat162float(hh));
    }
}

// ---------------- mma.sync bf16-split GEMM (pre + logits), 2 CTAs/SM ----------------
#define MM_LD 40
#define MM_MS (128*MM_LD)
#define MM_STG (4*MM_MS)

template<int MODE>
__global__ __launch_bounds__(256, 2)
void mma_gemm(const bf16* __restrict__ Ah, const bf16* __restrict__ Al,
              const bf16* __restrict__ Bh, const bf16* __restrict__ Bl,
              const float* __restrict__ bias, float* __restrict__ C, int N)
{
    extern __shared__ __align__(16) bf16 sm[];
    const int tid = threadIdx.x, w = tid >> 5, l = tid & 31;
    const int m0 = blockIdx.x * 128, n0 = blockIdx.y * 128;
    const int mw = (w >> 2) * 64, nw = (w & 3) * 32;
    const unsigned sbase = smem_u32(sm);

    float acc[4][4][4];
    #pragma unroll
    for (int i = 0; i < 4; ++i)
        #pragma unroll
        for (int j = 0; j < 4; ++j)
            #pragma unroll
            for (int q = 0; q < 4; ++q) acc[i][j][q] = 0.f;

    auto stage_load = [&](int c, int s) {
        int kc = c * 32;
        unsigned sb = sbase + (unsigned)(s * MM_STG) * 2;
        #pragma unroll
        for (int l2 = 0; l2 < 2; ++l2) {
            int u = tid + l2 * 256;
            int row = u >> 2, q = u & 3;
            unsigned soff = (unsigned)(row * MM_LD + q * 8) * 2;
            size_t ga = (size_t)(m0 + row) * 1024 + kc + q * 8;
            size_t gb = (size_t)(n0 + row) * 1024 + kc + q * 8;
            cpa16(sb + 0 * MM_MS * 2 + soff, Ah + ga);
            cpa16(sb + 1 * MM_MS * 2 + soff, Al + ga);
            cpa16(sb + 2 * MM_MS * 2 + soff, Bh + gb);
            cpa16(sb + 3 * MM_MS * 2 + soff, Bl + gb);
        }
    };

    stage_load(0, 0);
    asm volatile("cp.async.commit_group;" ::: "memory");
    const int ldrow = ((l >> 3) & 1) * 8 + (l & 7);
    const int ldcol = (l >> 4) * 8;

    for (int c = 0; c < 32; ++c) {
        if (c + 1 < 32) {
            stage_load(c + 1, (c + 1) & 1);
            asm volatile("cp.async.commit_group;" ::: "memory");
            asm volatile("cp.async.wait_group 1;" ::: "memory");
        } else {
            asm volatile("cp.async.wait_group 0;" ::: "memory");
        }
        __syncthreads();
        unsigned sb = sbase + (unsigned)((c & 1) * MM_STG) * 2;
        #pragma unroll
        for (int kk = 0; kk < 2; ++kk) {
            unsigned aH[4][4], aL[4][4], bH[4][2], bL[4][2];
            #pragma unroll
            for (int mt = 0; mt < 4; ++mt) {
                int r = mw + mt * 16 + ldrow;
                unsigned ad = sb + (unsigned)(r * MM_LD + kk * 16 + ldcol) * 2;
                ldsm4(aH[mt], ad);
                ldsm4(aL[mt], ad + MM_MS * 2);
            }
            #pragma unroll
            for (int p = 0; p < 2; ++p) {
                int r = nw + p * 16 + ldrow;
                unsigned bd = sb + (unsigned)(2 * MM_MS + r * MM_LD + kk * 16 + ldcol) * 2;
                unsigned t0[4], t1[4];
                ldsm4(t0, bd);
                ldsm4(t1, bd + MM_MS * 2);
                bH[2*p][0] = t0[0]; bH[2*p][1] = t0[2];
                bH[2*p+1][0] = t0[1]; bH[2*p+1][1] = t0[3];
                bL[2*p][0] = t1[0]; bL[2*p][1] = t1[2];
                bL[2*p+1][0] = t1[1]; bL[2*p+1][1] = t1[3];
            }
            #pragma unroll
            for (int mt = 0; mt < 4; ++mt)
                #pragma unroll
                for (int nt = 0; nt < 4; ++nt) {
                    mma16816(acc[mt][nt], aH[mt], bH[nt][0], bH[nt][1]);
                    mma16816(acc[mt][nt], aH[mt], bL[nt][0], bL[nt][1]);
                    mma16816(acc[mt][nt], aL[mt], bH[nt][0], bH[nt][1]);
                }
        }
        __syncthreads();
    }

    int g = l >> 2, tg = l & 3;
    #pragma unroll
    for (int mt = 0; mt < 4; ++mt) {
        int r0 = m0 + mw + mt * 16 + g;
        int r1 = r0 + 8;
        float *crow0, *crow1;
        if (MODE == 0) {
            crow0 = C + (size_t)r0 * N;
            crow1 = C + (size_t)r1 * N;
        } else {
            crow0 = C + ((size_t)(r0 & 127) * TSEQ + (r0 >> 7)) * N;
            crow1 = C + ((size_t)(r1 & 127) * TSEQ + (r1 >> 7)) * N;
        }
        #pragma unroll
        for (int nt = 0; nt < 4; ++nt) {
            int n = n0 + nw + nt * 8 + tg * 2;
            if (MODE == 0 || n < N) {
                float2 bv = *(const float2*)&bias[n];
                *(float2*)&crow0[n] = make_float2(acc[mt][nt][0] + bv.x, acc[mt][nt][1] + bv.y);
                *(float2*)&crow1[n] = make_float2(acc[mt][nt][2] + bv.x, acc[mt][nt][3] + bv.y);
            }
        }
    }
}

// ---------------- recurrence MMA tile ----------------
__device__ __noinline__ void rec_mma(
    const bf16* Ah, const bf16* Al, int akoff,
    const bf16* Bh, const bf16* Bl, int bkoff, int ldb,
    int n0, int kchunks, float* outp, int outW, bf16* sm)
{
    const int tid = threadIdx.x, w = tid >> 5, l = tid & 31;
    const int mw = (w >> 2) * 64, nw = (w & 3) * 32;
    const unsigned sbase = smem_u32(sm);

    float acc[4][4][4];
    #pragma unroll
    for (int i = 0; i < 4; ++i)
        #pragma unroll
        for (int j = 0; j < 4; ++j)
            #pragma unroll
            for (int q = 0; q < 4; ++q) acc[i][j][q] = 0.f;

    auto stage_load = [&](int c, int s) {
        int kc = c * 32;
        unsigned sb = sbase + (unsigned)(s * MM_STG) * 2;
        #pragma unroll
        for (int l2 = 0; l2 < 2; ++l2) {
            int u = tid + l2 * 256;
            int row = u >> 2, q = u & 3;
            unsigned soff = (unsigned)(row * MM_LD + q * 8) * 2;
            size_t ga = (size_t)row * 1024 + akoff + kc + q * 8;
            size_t gb = (size_t)(n0 + row) * ldb + bkoff + kc + q * 8;
            cpg16(sb + 0 * MM_MS * 2 + soff, Ah + ga);
            cpg16(sb + 1 * MM_MS * 2 + soff, Al + ga);
            cpg16(sb + 2 * MM_MS * 2 + soff, Bh + gb);
            cpg16(sb + 3 * MM_MS * 2 + soff, Bl + gb);
        }
    };

    stage_load(0, 0);
    asm volatile("cp.async.commit_group;" ::: "memory");
    const int ldrow = ((l >> 3) & 1) * 8 + (l & 7);
    const int ldcol = (l >> 4) * 8;

    for (int c = 0; c < kchunks; ++c) {
        if (c + 1 < kchunks) {
            stage_load(c + 1, (c + 1) & 1);
            asm volatile("cp.async.commit_group;" ::: "memory");
            asm volatile("cp.async.wait_group 1;" ::: "memory");
        } else {
            asm volatile("cp.async.wait_group 0;" ::: "memory");
        }
        __syncthreads();
        unsigned sb = sbase + (unsigned)((c & 1) * MM_STG) * 2;
        #pragma unroll
        for (int kk = 0; kk < 2; ++kk) {
            unsigned aH[4][4], aL[4][4], bH[4][2], bL[4][2];
            #pragma unroll
            for (int mt = 0; mt < 4; ++mt) {
                int r = mw + mt * 16 + ldrow;
                unsigned ad = sb + (unsigned)(r * MM_LD + kk * 16 + ldcol) * 2;
                ldsm4(aH[mt], ad);
                ldsm4(aL[mt], ad + MM_MS * 2);
            }
            #pragma unroll
            for (int p = 0; p < 2; ++p) {
                int r = nw + p * 16 + ldrow;
                unsigned bd = sb + (unsigned)(2 * MM_MS + r * MM_LD + kk * 16 + ldcol) * 2;
                unsigned t0[4], t1[4];
                ldsm4(t0, bd);
                ldsm4(t1, bd + MM_MS * 2);
                bH[2*p][0] = t0[0]; bH[2*p][1] = t0[2];
                bH[2*p+1][0] = t0[1]; bH[2*p+1][1] = t0[3];
                bL[2*p][0] = t1[0]; bL[2*p][1] = t1[2];
                bL[2*p+1][0] = t1[1]; bL[2*p+1][1] = t1[3];
            }
            #pragma unroll
            for (int mt = 0; mt < 4; ++mt)
                #pragma unroll
                for (int nt = 0; nt < 4; ++nt) {
                    mma16816(acc[mt][nt], aH[mt], bH[nt][0], bH[nt][1]);
                    mma16816(acc[mt][nt], aH[mt], bL[nt][0], bL[nt][1]);
                    mma16816(acc[mt][nt], aL[mt], bH[nt][0], bH[nt][1]);
                }
        }
        __syncthreads();
    }

    int g = l >> 2, tg = l & 3;
    #pragma unroll
    for (int mt = 0; mt < 4; ++mt) {
        int r0 = mw + mt * 16 + g;
        int r1 = r0 + 8;
        #pragma unroll
        for (int nt = 0; nt < 4; ++nt) {
            int n = n0 + nw + nt * 8 + tg * 2;
            *(float2*)&outp[(size_t)r0 * outW + n] = make_float2(acc[mt][nt][0], acc[mt][nt][1]);
            *(float2*)&outp[(size_t)r1 * outW + n] = make_float2(acc[mt][nt][2], acc[mt][nt][3]);
        }
    }
}

// ---------------- persistent recurrence ----------------
struct RecParams {
    const float *bu1, *br1, *bc1;
};

__device__ __forceinline__ void grid_barrier(unsigned& sense) {
    __syncthreads();
    if (threadIdx.x == 0) {
        unsigned next = sense ^ 1u;
        __threadfence();
        if (atomicAdd(&g_barcnt, 1u) == NBLK - 1) {
            g_barcnt = 0;
            __threadfence();
            g_barsense = next;
        } else {
            while (g_barsense != next) __nanosleep(32);
        }
    }
    sense ^= 1u;
    __syncthreads();
}

__global__ __launch_bounds__(256, 1)
void recurrence_kernel(RecParams P)
{
    extern __shared__ __align__(16) bf16 sm[];
    unsigned sense = 0;
    const int bid = blockIdx.x;
    const int tid = threadIdx.x;

    for (int t = 0; t < TSEQ; ++t) {
        const int cur = t & 1, nxt = cur ^ 1;
        const float* xp = g_xp + (size_t)t * BATCH * XP3;
        float* h0c = g_h0buf + (size_t)cur * BH;
        float* h0n = g_h0buf + (size_t)nxt * BH;
        float* h1c = g_h1buf + (size_t)cur * BH;
        float* h1n = g_h1buf + (size_t)nxt * BH;
        bf16 *h0ch = g_h0h + (size_t)cur * BH, *h0cl = g_h0l + (size_t)cur * BH;
        bf16 *h0nh = g_h0h + (size_t)nxt * BH, *h0nl = g_h0l + (size_t)nxt * BH;
        bf16 *h1ch = g_h1h + (size_t)cur * BH, *h1cl = g_h1l + (size_t)cur * BH;
        bf16 *h1nh = g_h1h + (size_t)nxt * BH, *h1nl = g_h1l + (size_t)nxt * BH;

        // Phase A: layer0 u,r h-part -> pA
        if (bid < 128) {
            int gg = bid >> 6, ks = bid & 7, nt = (bid >> 3) & 7;
            rec_mma(h0ch, h0cl, ks * 128,
                    g_wt0h + (size_t)gg * 1024 * 1024, g_wt0l + (size_t)gg * 1024 * 1024,
                    ks * 128, 1024, nt * 128, 4,
                    g_pA + (size_t)ks * 128 * 2048 + gg * 1024, 2048, sm);
        }
        grid_barrier(sense);

        // ACT A: rh0 = sig(xr + sum pA[r]) * h0c
        for (int i = bid * 256 + tid; i < BH / 2; i += NBLK * 256) {
            size_t idx = (size_t)i * 2;
            int m = (int)(idx >> 10), n = (int)(idx & 1023);
            float2 s = *(const float2*)&xp[(size_t)m * XP3 + 1024 + n];
            #pragma unroll
            for (int p = 0; p < 8; ++p) {
                float2 v = __ldcg((const float2*)&g_pA[((size_t)p * 128 + m) * 2048 + 1024 + n]);
                s.x += v.x; s.y += v.y;
            }
            float2 h = __ldcg((const float2*)&h0c[idx]);
            bsplit2(g_rh0h, g_rh0l, idx, make_float2(sigf(s.x) * h.x, sigf(s.y) * h.y));
        }
        grid_barrier(sense);

        // Phase B: layer0 candidate -> pB
        if (bid < 128) {
            int ks = bid & 15, nt = bid >> 4;
            rec_mma(g_rh0h, g_rh0l, ks * 64,
                    g_wt0h + (size_t)2 * 1024 * 1024, g_wt0l + (size_t)2 * 1024 * 1024,
                    ks * 64, 1024, nt * 128, 2,
                    g_pB + (size_t)ks * 128 * 1024, 1024, sm);
        }
        grid_barrier(sense);

        // ACT B: h0n = u*h0c + (1-u)*tanh(xc + sum pB)
        for (int i = bid * 256 + tid; i < BH / 2; i += NBLK * 256) {
            size_t idx = (size_t)i * 2;
            int m = (int)(idx >> 10), n = (int)(idx & 1023);
            float2 su = *(const float2*)&xp[(size_t)m * XP3 + n];
            #pragma unroll
            for (int p = 0; p < 8; ++p) {
                float2 v = __ldcg((const float2*)&g_pA[((size_t)p * 128 + m) * 2048 + n]);
                su.x += v.x; su.y += v.y;
            }
            float2 sc = *(const float2*)&xp[(size_t)m * XP3 + 2048 + n];
            #pragma unroll
            for (int p = 0; p < 16; ++p) {
                float2 v = __ldcg((const float2*)&g_pB[((size_t)p * 128 + m) * 1024 + n]);
                sc.x += v.x; sc.y += v.y;
            }
            float2 h = __ldcg((const float2*)&h0c[idx]);
            float ux = sigf(su.x), uy = sigf(su.y);
            float2 o = make_float2(ux * h.x + (1.f - ux) * tanhf(sc.x),
                                   uy * h.y + (1.f - uy) * tanhf(sc.y));
            *(float2*)&h0n[idx] = o;
            bsplit2(h0nh, h0nl, idx, o);
        }
        grid_barrier(sense);

        // Phase C: layer1 u,r over [h0n | h1c] -> pC
        if (bid < 128) {
            int gg = bid >> 6, ks = bid & 7, nt = (bid >> 3) & 7;
            int koff = ks * 256;
            const bf16* ah = (koff < 1024) ? h0nh : h1ch;
            const bf16* al = (koff < 1024) ? h0nl : h1cl;
            rec_mma(ah, al, koff & 1023,
                    g_wt1h + (size_t)gg * 1024 * 2048, g_wt1l + (size_t)gg * 1024 * 2048,
                    koff, 2048, nt * 128, 8,
                    g_pC + (size_t)ks * 128 * 2048 + gg * 1024, 2048, sm);
        }
        grid_barrier(sense);

        // ACT C: rh1 = sig(br1 + sum pC[r]) * h1c
        for (int i = bid * 256 + tid; i < BH / 2; i += NBLK * 256) {
            size_t idx = (size_t)i * 2;
            int m = (int)(idx >> 10), n = (int)(idx & 1023);
            float2 s = *(const float2*)&P.br1[n];
            #pragma unroll
            for (int p = 0; p < 8; ++p) {
                float2 v = __ldcg((const float2*)&g_pC[((size_t)p * 128 + m) * 2048 + 1024 + n]);
                s.x += v.x; s.y += v.y;
            }
            float2 h = __ldcg((const float2*)&h1c[idx]);
            bsplit2(g_rh1h, g_rh1l, idx, make_float2(sigf(s.x) * h.x, sigf(s.y) * h.y));
        }
        grid_barrier(sense);

        // Phase D: layer1 candidate over [h0n | rh1] -> pD
        if (bid < 128) {
            int ks = bid & 15, nt = bid >> 4;
            int koff = ks * 128;
            const bf16* ah = (koff < 1024) ? h0nh : g_rh1h;
            const bf16* al = (koff < 1024) ? h0nl : g_rh1l;
            rec_mma(ah, al, koff & 1023,
                    g_wt1h + (size_t)2 * 1024 * 2048, g_wt1l + (size_t)2 * 1024 * 2048,
                    koff, 2048, nt * 128, 4,
                    g_pD + (size_t)ks * 128 * 1024, 1024, sm);
        }
        grid_barrier(sense);

        // ACT D: h1n = u1*h1c + (1-u1)*tanh(bc1 + sum pD)
        {
            float* seq = g_h1seq + (size_t)t * BH;
            for (int i = bid * 256 + tid; i < BH / 2; i += NBLK * 256) {
                size_t idx = (size_t)i * 2;
                int m = (int)(idx >> 10), n = (int)(idx & 1023);
                float2 su = *(const float2*)&P.bu1[n];
                #pragma unroll
                for (int p = 0; p < 8; ++p) {
                    float2 v = __ldcg((const float2*)&g_pC[((size_t)p * 128 + m) * 2048 + n]);
                    su.x += v.x; su.y += v.y;
                }
                float2 sc = *(const float2*)&P.bc1[n];
                #pragma unroll
                for (int p = 0; p < 16; ++p) {
                    float2 v = __ldcg((const float2*)&g_pD[((size_t)p * 128 + m) * 1024 + n]);
                    sc.x += v.x; sc.y += v.y;
                }
                float2 h = __ldcg((const float2*)&h1c[idx]);
                float ux = sigf(su.x), uy = sigf(su.y);
                float2 o = make_float2(ux * h.x + (1.f - ux) * tanhf(sc.x),
                                       uy * h.y + (1.f - uy) * tanhf(sc.y));
                *(float2*)&h1n[idx] = o;
                *(float2*)&seq[idx] = o;
                bsplit2(h1nh, h1nl, idx, o);
            }
        }
        grid_barrier(sense);
    }
}

// ---------------- host orchestration ----------------
extern "C" void kernel_launch(void* const* d_in, const int* in_sizes, int n_in,
                              void* d_out, int out_size)
{
    const int*   tok  = (const int*)  d_in[0];
    const float* ihs  = (const float*)d_in[1];
    const float* emb  = (const float*)d_in[2];
    const float* Wout = (const float*)d_in[3];
    const float* bout = (const float*)d_in[4];
    const float* wu0  = (const float*)d_in[5];
    const float* bu0  = (const float*)d_in[6];
    const float* wr0  = (const float*)d_in[7];
    const float* br0  = (const float*)d_in[8];
    const float* wc0  = (const float*)d_in[9];
    const float* bc0  = (const float*)d_in[10];
    const float* wu1  = (const float*)d_in[11];
    const float* bu1  = (const float*)d_in[12];
    const float* wr1  = (const float*)d_in[13];
    const float* br1  = (const float*)d_in[14];
    const float* wc1  = (const float*)d_in[15];
    const float* bc1  = (const float*)d_in[16];

    float *p_x, *p_xp, *p_seq, *p_bias3;
    bf16 *p_ah, *p_al, *p_bth, *p_btl, *p_wt0h, *p_wt0l, *p_wt1h, *p_wt1l;
    cudaGetSymbolAddress((void**)&p_x,    g_x);
    cudaGetSymbolAddress((void**)&p_xp,   g_xp);
    cudaGetSymbolAddress((void**)&p_seq,  g_h1seq);
    cudaGetSymbolAddress((void**)&p_bias3, g_bias3);
    cudaGetSymbolAddress((void**)&p_ah,  g_ah);
    cudaGetSymbolAddress((void**)&p_al,  g_al);
    cudaGetSymbolAddress((void**)&p_bth, g_bth);
    cudaGetSymbolAddress((void**)&p_btl, g_btl);
    cudaGetSymbolAddress((void**)&p_wt0h, g_wt0h);
    cudaGetSymbolAddress((void**)&p_wt0l, g_wt0l);
    cudaGetSymbolAddress((void**)&p_wt1h, g_wt1h);
    cudaGetSymbolAddress((void**)&p_wt1l, g_wt1l);

    const int MM_SMEM = 2 * MM_STG * 2;   // 81920 B
    cudaFuncSetAttribute(mma_gemm<0>, cudaFuncAttributeMaxDynamicSharedMemorySize, MM_SMEM);
    cudaFuncSetAttribute(mma_gemm<1>, cudaFuncAttributeMaxDynamicSharedMemorySize, MM_SMEM);
    cudaFuncSetAttribute(recurrence_kernel, cudaFuncAttributeMaxDynamicSharedMemorySize, MM_SMEM);

    // 1) gather embeddings
    gather_kernel<<<TSEQ * BATCH, 256>>>(tok, emb);

    // 2) fused pre: one GEMM for all 3 layer-0 x-projections (N = 3072)
    int n4 = TSEQ * BH / 4;
    cvt_split<<<(n4 + 255) / 256, 256>>>(p_x, p_ah, p_al, n4);
    dim3 tb(32, 8);
    tconv<<<dim3(32, 32), tb>>>(wu0, HID, HID, 1024, p_bth,               p_btl);
    tconv<<<dim3(32, 32), tb>>>(wr0, HID, HID, 1024, p_bth + 1024*1024,   p_btl + 1024*1024);
    tconv<<<dim3(32, 32), tb>>>(wc0, HID, HID, 1024, p_bth + 2*1024*1024, p_btl + 2*1024*1024);
    concat_bias<<<4, 256>>>(bu0, br0, bc0);
    mma_gemm<0><<<dim3(64, XP3 / 128), 256, MM_SMEM>>>(p_ah, p_al, p_bth, p_btl,
                                                        p_bias3, p_xp, XP3);

    // 3) recurrence weight transposes
    const size_t EH = (size_t)EMB * HID;
    tconv<<<dim3(32, 32), tb>>>(wu0 + EH, HID, HID, 1024, p_wt0h,               p_wt0l);
    tconv<<<dim3(32, 32), tb>>>(wr0 + EH, HID, HID, 1024, p_wt0h + 1024*1024,   p_wt0l + 1024*1024);
    tconv<<<dim3(32, 32), tb>>>(wc0 + EH, HID, HID, 1024, p_wt0h + 2*1024*1024, p_wt0l + 2*1024*1024);
    tconv<<<dim3(32, 64), tb>>>(wu1, HID, HID, 2048, p_wt1h,               p_wt1l);
    tconv<<<dim3(32, 64), tb>>>(wr1, HID, HID, 2048, p_wt1h + 1024*2048,   p_wt1l + 1024*2048);
    tconv<<<dim3(32, 64), tb>>>(wc1, HID, HID, 2048, p_wt1h + 2*1024*2048, p_wt1l + 2*1024*2048);

    // 4) initial hidden state
    init_h<<<(BH / 2 + 255) / 256, 256>>>(ihs);

    // 5) persistent recurrence
    RecParams P{bu1, br1, bc1};
    recurrence_kernel<<<NBLK, 256, MM_SMEM>>>(P);

    // 6) output projection
    cvt_split<<<(n4 + 255) / 256, 256>>>(p_seq, p_ah, p_al, n4);
    tconv<<<dim3(NPAD / 32, 32), tb>>>(Wout, VOCAB, VOCAB, 1024, p_bth, p_btl);
    mma_gemm<1><<<dim3(64, NPAD / 128), 256, MM_SMEM>>>(p_ah, p_al, p_bth, p_btl,
                                                         bout, (float*)d_out, VOCAB);

    // 7) final states
    state_out<<<(BH + 255) / 256, 256>>>((float*)d_out, (long long)out_size);
}